// round 11
// baseline (speedup 1.0000x reference)
#include <cuda_runtime.h>
#include <cuda_fp16.h>
#include <math.h>
#include <stdint.h>

#define NE  800000
#define NN  50000
#define HID 128

// ---------------- scratch (static device globals; no allocation) ----------------
__device__ float4 g_xh4[NN * 32];     // xh = x@W_x + b_x, [N,128] as float4
__device__ float  g_wV [NN * 128];    // scatter-add accumulator
__device__ float  g_deg[NN];          // degree accumulator
// fragment-linear fp16 B operands, uint4 = frags for n-tile pair {2p, 2p+1}
__device__ uint4  g_fWin[8 * 2 * 32];    // 8 KB  (K padded to 32, zeros past 24)
__device__ uint4  g_fW1 [8 * 8 * 32];    // 32 KB
__device__ uint4  g_fW2 [8 * 8 * 32];    // 32 KB
__device__ uint4  g_fWf [8 * 8 * 32];    // 32 KB

// ---------------- SMEM layout (edge kernel, dynamic) ----------------
#define OFF_A    0          // 32KB A tile: 128 rows x 128 fp16 (256B/row), XOR-swizzled
#define OFF_PE   32768      // 8KB  pe tile: 128 rows x 32 fp16 (64B/row)
#define OFF_B0   40960      // 32KB frag buffer 0
#define OFF_B1   73728      // 32KB frag buffer 1
#define OFF_BIAS 106496     // 2KB: 4 stages x 128 floats
#define OFF_IDX  108544     // 1KB: tgt[128], src[128]
#define SMEM_TOT 109568
// scores overlay: fp32 [128][128] over B0+B1 (64KB exactly)

// ---------------- helpers ----------------
__device__ __forceinline__ uint32_t packh2(float lo, float hi) {
    __half2 h = __floats2half2_rn(lo, hi);
    return *(uint32_t*)&h;
}
// GELU exact-erf via Abramowitz-Stegun 7.1.26 (|err|<=1.5e-7), branchless.
__device__ __forceinline__ float gelu_f(float x) {
    float th = 0.5f * x;
    float u  = th * x;                                    // t^2 = x^2/2
    float at = 0.7071067811865476f * fabsf(x);            // t >= 0
    float d  = fmaf(0.3275911f, at, 1.0f);
    float k;  asm("rcp.approx.f32 %0, %1;" : "=f"(k) : "f"(d));
    float p = fmaf(1.061405429f, k, -1.453152027f);
    p = fmaf(p, k, 1.421413741f);
    p = fmaf(p, k, -0.284496736f);
    p = fmaf(p, k, 0.254829592f);
    p = p * k;
    float s  = p * __expf(-u);                            // = 1 - erf(t)
    float ah = fabsf(th);
    return (th + ah) - ah * s;
}
__device__ __forceinline__ void red4(float* p, float a, float b, float c, float d) {
    asm volatile("red.global.add.v4.f32 [%0], {%1,%2,%3,%4};"
                 :: "l"(p), "f"(a), "f"(b), "f"(c), "f"(d) : "memory");
}
__device__ __forceinline__ void red1(float* p, float v) {
    asm volatile("red.global.add.f32 [%0], %1;" :: "l"(p), "f"(v) : "memory");
}
__device__ __forceinline__ uint32_t s2u(const void* p) {
    uint32_t a;
    asm("{ .reg .u64 t; cvta.to.shared.u64 t, %1; cvt.u32.u64 %0, t; }" : "=r"(a) : "l"(p));
    return a;
}
__device__ __forceinline__ void cp16(uint32_t s, const void* g) {
    asm volatile("cp.async.cg.shared.global [%0], [%1], 16;" :: "r"(s), "l"(g));
}
#define CP_COMMIT() asm volatile("cp.async.commit_group;")
#define CP_WAIT(n)  asm volatile("cp.async.wait_group %0;" :: "n"(n) : "memory")

__device__ __forceinline__ void mma16(float d[4], const uint32_t a[4],
                                      uint32_t b0, uint32_t b1) {
    asm volatile(
        "mma.sync.aligned.m16n8k16.row.col.f32.f16.f16.f32 "
        "{%0,%1,%2,%3},{%4,%5,%6,%7},{%8,%9},{%0,%1,%2,%3};"
        : "+f"(d[0]), "+f"(d[1]), "+f"(d[2]), "+f"(d[3])
        : "r"(a[0]), "r"(a[1]), "r"(a[2]), "r"(a[3]), "r"(b0), "r"(b1));
}
__device__ __forceinline__ void ldm4(uint32_t a[4], uint32_t saddr) {
    asm volatile("ldmatrix.sync.aligned.m8n8.x4.shared.b16 {%0,%1,%2,%3}, [%4];"
                 : "=r"(a[0]), "=r"(a[1]), "=r"(a[2]), "=r"(a[3]) : "r"(saddr));
}

// ---------------- weight prep: fragment-linear fp16 B arrays (uint4 pairs) ----------------
__global__ void __launch_bounds__(256)
prep_kernel(const float* __restrict__ W_in, const float* __restrict__ W1,
            const float* __restrict__ W2,   const float* __restrict__ Wf)
{
    int idx = blockIdx.x * 256 + threadIdx.x;
    if (idx < 512) {                          // Win: pg(8) x ks(2) x lane(32)
        int lane = idx & 31, ks = (idx >> 5) & 1, pg = idx >> 6;
        int k0 = ks * 16 + 2 * (lane & 3);
        int n0 = pg * 16 + (lane >> 2), n1 = n0 + 8;
        uint4 u;
        u.x = packh2(k0     < 24 ? W_in[k0 * 128 + n0]       : 0.f,
                     k0 + 1 < 24 ? W_in[(k0 + 1) * 128 + n0] : 0.f);
        u.y = packh2(k0 + 8 < 24 ? W_in[(k0 + 8) * 128 + n0] : 0.f,
                     k0 + 9 < 24 ? W_in[(k0 + 9) * 128 + n0] : 0.f);
        u.z = packh2(k0     < 24 ? W_in[k0 * 128 + n1]       : 0.f,
                     k0 + 1 < 24 ? W_in[(k0 + 1) * 128 + n1] : 0.f);
        u.w = packh2(k0 + 8 < 24 ? W_in[(k0 + 8) * 128 + n1] : 0.f,
                     k0 + 9 < 24 ? W_in[(k0 + 9) * 128 + n1] : 0.f);
        g_fWin[(pg * 2 + ks) * 32 + lane] = u;
    } else {
        int r = idx - 512;
        if (r >= 3 * 2048) return;
        int sel = r >> 11; r &= 2047;
        int lane = r & 31, ks = (r >> 5) & 7, pg = r >> 8;
        int k0 = ks * 16 + 2 * (lane & 3);
        int n0 = pg * 16 + (lane >> 2), n1 = n0 + 8;
        const float* W = (sel == 0) ? W1 : (sel == 1) ? W2 : Wf;
        uint4* F       = (sel == 0) ? g_fW1 : (sel == 1) ? g_fW2 : g_fWf;
        uint4 u;
        u.x = packh2(W[k0 * 128 + n0],       W[(k0 + 1) * 128 + n0]);
        u.y = packh2(W[(k0 + 8) * 128 + n0], W[(k0 + 9) * 128 + n0]);
        u.z = packh2(W[k0 * 128 + n1],       W[(k0 + 1) * 128 + n1]);
        u.w = packh2(W[(k0 + 8) * 128 + n1], W[(k0 + 9) * 128 + n1]);
        F[(pg * 8 + ks) * 32 + lane] = u;
    }
}

// ---------------- degree histogram (independent of edge MLP) ----------------
__global__ void __launch_bounds__(256)
deg_kernel(const int* __restrict__ pe_index, float* __restrict__ deg)
{
    int i = blockIdx.x * 1024 + threadIdx.x;
#pragma unroll
    for (int j = 0; j < 4; j++) {
        int e = i + j * 256;
        if (e < NE) red1(deg + pe_index[e], 1.0f);
    }
}

// ---------------- MMA stage: warp tile m32 x n32, ldmatrix A + uint4 B ----------------
// A tile: 256B/row, 16B chunk q at physical chunk q^(row&7).
template<int KS>
__device__ __forceinline__ void mma_stageA(
    float acc[2][4][4], uint32_t ra0, uint32_t ra1, int hi, int rs,
    const uint4* F, int nq, int lane)
{
#pragma unroll
    for (int ks = 0; ks < KS; ks++) {
        uint32_t a0[4], a1[4];
        uint32_t off = (uint32_t)(((2 * ks + hi) ^ rs) << 4);
        ldm4(a0, ra0 + off);
        ldm4(a1, ra1 + off);
#pragma unroll
        for (int p = 0; p < 2; p++) {
            uint4 b = F[((nq * 2 + p) * KS + ks) * 32 + lane];
            mma16(acc[0][2*p],   a0, b.x, b.y);
            mma16(acc[1][2*p],   a1, b.x, b.y);
            mma16(acc[0][2*p+1], a0, b.z, b.w);
            mma16(acc[1][2*p+1], a1, b.z, b.w);
        }
    }
}

// PE tile: 64B/row (4 chunks), chunk q at physical q^((row>>1)&3).
__device__ __forceinline__ void mma_stagePE(
    float acc[2][4][4], uint32_t rp0, uint32_t rp1, int hi, int swp,
    const uint4* __restrict__ FWin, int nq, int lane)
{
#pragma unroll
    for (int ks = 0; ks < 2; ks++) {
        uint32_t a0[4], a1[4];
        uint32_t off = (uint32_t)(((2 * ks + hi) ^ swp) << 4);
        ldm4(a0, rp0 + off);
        ldm4(a1, rp1 + off);
#pragma unroll
        for (int p = 0; p < 2; p++) {
            uint4 b = __ldg(&FWin[((nq * 2 + p) * 2 + ks) * 32 + lane]);
            mma16(acc[0][2*p],   a0, b.x, b.y);
            mma16(acc[1][2*p],   a1, b.x, b.y);
            mma16(acc[0][2*p+1], a0, b.z, b.w);
            mma16(acc[1][2*p+1], a1, b.z, b.w);
        }
    }
}

__device__ __forceinline__ void zero_acc(float acc[2][4][4]) {
#pragma unroll
    for (int mt = 0; mt < 2; mt++)
#pragma unroll
        for (int nt = 0; nt < 4; nt++)
#pragma unroll
            for (int i = 0; i < 4; i++) acc[mt][nt][i] = 0.f;
}

// MODE 0: gelu -> fp16 store to A; MODE 1: plain fp16 store to A
template<int MODE>
__device__ __forceinline__ void epilogueH(
    float acc[2][4][4], const float* bias, uint32_t* A32,
    int mbase, int nbase, int g, int t)
{
#pragma unroll
    for (int nt = 0; nt < 4; nt++) {
        int c = nbase + nt * 8 + 2 * t;
        float2 bb = *(const float2*)(bias + c);
        int c2 = c >> 1;
        int w  = (((c2 >> 2) ^ g) << 2) + (c2 & 3);
#pragma unroll
        for (int mt = 0; mt < 2; mt++) {
            int r0 = mbase + mt * 16 + g;
            float v0 = acc[mt][nt][0] + bb.x, v1 = acc[mt][nt][1] + bb.y;
            float v2 = acc[mt][nt][2] + bb.x, v3 = acc[mt][nt][3] + bb.y;
            if (MODE == 0) {
                v0 = gelu_f(v0); v1 = gelu_f(v1);
                v2 = gelu_f(v2); v3 = gelu_f(v3);
            }
            A32[r0 * 64 + w]       = packh2(v0, v1);
            A32[(r0 + 8) * 64 + w] = packh2(v2, v3);
        }
    }
}

// scores epilogue: fp32 into S with per-row 16B-chunk XOR swizzle
__device__ __forceinline__ void epilogueS(
    float acc[2][4][4], const float* bias, float* S,
    int mbase, int nbase, int g, int t)
{
#pragma unroll
    for (int nt = 0; nt < 4; nt++) {
        int c = nbase + nt * 8 + 2 * t;
        float2 bb = *(const float2*)(bias + c);
        int w = (((c >> 2) ^ g) << 2) + (c & 3);
#pragma unroll
        for (int mt = 0; mt < 2; mt++) {
            int r0 = mbase + mt * 16 + g;
            *(float2*)(S + r0 * 128 + w) =
                make_float2(acc[mt][nt][0] + bb.x, acc[mt][nt][1] + bb.y);
            *(float2*)(S + (r0 + 8) * 128 + w) =
                make_float2(acc[mt][nt][2] + bb.x, acc[mt][nt][3] + bb.y);
        }
    }
}

// ---------------- fused edge kernel (mma.sync fp16, 512 thr, 2 CTAs/SM) ----------------
__global__ void __launch_bounds__(512, 2)
edge_kernel(const int* __restrict__ pe_index, const float* __restrict__ pe_val,
            const float* __restrict__ b_in, const float* __restrict__ b1,
            const float* __restrict__ b2,   const float* __restrict__ bf,
            const float4* __restrict__ xh4,
            float* __restrict__ wV)
{
    extern __shared__ char smem[];
    uint32_t sm = s2u(smem);
    uint32_t* A32   = (uint32_t*)(smem + OFF_A);
    uint32_t* PE32  = (uint32_t*)(smem + OFF_PE);
    const uint4* F0 = (const uint4*)(smem + OFF_B0);
    const uint4* F1 = (const uint4*)(smem + OFF_B1);
    float* sBias    = (float*)(smem + OFF_BIAS);
    int*   sIdx     = (int*)(smem + OFF_IDX);

    int tid  = threadIdx.x;
    int wid  = tid >> 5, lane = tid & 31;
    int mr   = wid & 3,  nq   = wid >> 2;     // 4 m-groups x 4 n-groups
    int g    = lane >> 2, t   = lane & 3;
    int mbase = mr * 32, nbase = nq * 32;
    int e0   = blockIdx.x * 128;

    // ldmatrix per-lane bases (A row = 256 bytes, PE row = 64 bytes)
    int l15 = lane & 15, hi = lane >> 4, rs = lane & 7;
    int swp = (l15 >> 1) & 3;
    uint32_t ra0 = sm + OFF_A  + (uint32_t)(mbase + l15) * 256;
    uint32_t ra1 = ra0 + 16 * 256;
    uint32_t rp0 = sm + OFF_PE + (uint32_t)(mbase + l15) * 64;
    uint32_t rp1 = rp0 + 16 * 64;

    // --- stage W1 -> B0, W2 -> B1 via cp.async (512 threads, 4 iters each) ---
#pragma unroll
    for (int i = 0; i < 4; i++)
        cp16(sm + OFF_B0 + (i * 512 + tid) * 16, (const char*)g_fW1 + (i * 512 + tid) * 16);
    CP_COMMIT();
#pragma unroll
    for (int i = 0; i < 4; i++)
        cp16(sm + OFF_B1 + (i * 512 + tid) * 16, (const char*)g_fW2 + (i * 512 + tid) * 16);
    CP_COMMIT();

    // --- indices + biases ---
    if (tid < 256)
        sIdx[tid] = (tid < 128) ? pe_index[e0 + tid] : pe_index[NE + e0 + (tid - 128)];
    {
        int st = tid >> 7, c = tid & 127;
        float v = (st == 0) ? b_in[c] : (st == 1) ? b1[c]
                : (st == 2) ? (b_in[c] + b2[c])   : bf[c];
        sBias[tid] = v;
    }

    // --- build PE tile (fp16, K 24 padded to 32): 4 threads/row, 1 chunk each ---
    {
        int row = tid >> 2, q = tid & 3;          // chunk q = cols 8q..8q+7
        uint32_t w0 = 0, w1 = 0, w2 = 0, w3 = 0;
        if (q < 3) {
            const float4* pr = (const float4*)(pe_val + (size_t)(e0 + row) * 24);
            float4 v0 = pr[2 * q], v1 = pr[2 * q + 1];
            w0 = packh2(v0.x, v0.y); w1 = packh2(v0.z, v0.w);
            w2 = packh2(v1.x, v1.y); w3 = packh2(v1.z, v1.w);
        }
        int sw = (row >> 1) & 3;
        uint32_t* base = PE32 + row * 16;
        *(uint4*)(base + ((q ^ sw) << 2)) = make_uint4(w0, w1, w2, w3);
    }

    float acc[2][4][4];
    __syncthreads();                                 // PE + bias + idx visible

    // ---- stage 1: acc = pe @ Win (Win frags from L2) ----
    zero_acc(acc);
    mma_stagePE(acc, rp0, rp1, hi, swp, g_fWin, nq, lane);
    epilogueH<0>(acc, sBias, A32, mbase, nbase, g, t);      // A = gelu(x0+b_in)
    CP_WAIT(1);                                              // W1 resident
    __syncthreads();

    // ---- stage 2: acc = A @ W1 ----
    zero_acc(acc);
    mma_stageA<8>(acc, ra0, ra1, hi, rs, F0, nq, lane);
    __syncthreads();                                         // B0+A reads done

    // prefetch Wf -> B0
#pragma unroll
    for (int i = 0; i < 4; i++)
        cp16(sm + OFF_B0 + (i * 512 + tid) * 16, (const char*)g_fWf + (i * 512 + tid) * 16);
    CP_COMMIT();

    epilogueH<0>(acc, sBias + 128, A32, mbase, nbase, g, t); // A = gelu(h+b1)
    CP_WAIT(1);                                              // W2 resident
    __syncthreads();

    // ---- stage 3: acc = A @ W2 + pe @ Win (K-concat residual) ----
    zero_acc(acc);
    mma_stageA<8>(acc, ra0, ra1, hi, rs, F1, nq, lane);
    mma_stagePE(acc, rp0, rp1, hi, swp, g_fWin, nq, lane);
    __syncthreads();                                         // A reads done
    epilogueH<1>(acc, sBias + 256, A32, mbase, nbase, g, t); // A = res
    CP_WAIT(0);                                              // Wf resident
    __syncthreads();

    // ---- stage 4: acc = A @ Wf ----
    zero_acc(acc);
    mma_stageA<8>(acc, ra0, ra1, hi, rs, F0, nq, lane);
    __syncthreads();                                         // B0 reads done
    float* S = (float*)(smem + OFF_B0);                      // scores overlay 64KB
    epilogueS(acc, sBias + 384, S, mbase, nbase, g, t);
    __syncthreads();

    // ---- scatter: msg = xh[src]*score -> wV[tgt]; 16 warps x 8 edges ----
#pragma unroll 4
    for (int i = 0; i < 8; i++) {
        int e    = wid * 8 + i;
        int tgt  = sIdx[e];
        int srcn = sIdx[128 + e];
        float4 xv = xh4[(size_t)srcn * 32 + lane];
        float4 s4 = *(const float4*)(S + e * 128 + ((lane ^ (e & 7)) << 2));
        red4(wV + (size_t)tgt * 128 + lane * 4,
             xv.x * s4.x, xv.y * s4.y, xv.z * s4.z, xv.w * s4.w);
    }
}

// ---------------- node projection: xh = x @ W_x + b_x (8 nodes/block) ----------------
__global__ void __launch_bounds__(128)
xh_kernel(const float* __restrict__ x, const float* __restrict__ Wx,
          const float* __restrict__ bx, float* __restrict__ xh)
{
    __shared__ float sx[8][64];
    int tid = threadIdx.x;
    int n0  = blockIdx.x * 8;
#pragma unroll
    for (int i = tid; i < 512; i += 128)
        sx[i >> 6][i & 63] = x[(size_t)n0 * 64 + i];
    __syncthreads();
    int c = tid;
    float s[8];
#pragma unroll
    for (int j = 0; j < 8; j++) s[j] = bx[c];
#pragma unroll 8
    for (int k = 0; k < 64; k++) {
        float w = Wx[k * 128 + c];
#pragma unroll
        for (int j = 0; j < 8; j++) s[j] += sx[j][k] * w;
    }
#pragma unroll
    for (int j = 0; j < 8; j++)
        xh[(size_t)(n0 + j) * 128 + c] = s[j];
}

// ---------------- output projection (16 nodes/block, 4 nodes/thread) ----------------
__global__ void __launch_bounds__(256)
out_kernel(const float* __restrict__ wV, const float* __restrict__ deg,
           const float* __restrict__ hb, const float* __restrict__ Wout,
           const float* __restrict__ bout, float* __restrict__ out)
{
    __shared__ float sh[16][128];
    int tid = threadIdx.x;
    int n0  = blockIdx.x * 16;
#pragma unroll
    for (int i = tid; i < 2048; i += 256) {
        int nn = i >> 7, k = i & 127;
        int n  = n0 + nn;
        float d = deg[n];
        float invd = 1.0f / (d > 1.0f ? d : 1.0f);
        sh[nn][k] = wV[(size_t)n * 128 + k] * invd + hb[k];
    }
    __syncthreads();
    int gg = tid >> 6, c = tid & 63;
    float s0 = bout[c], s1 = s0, s2 = s0, s3 = s0;
#pragma unroll 8
    for (int k = 0; k < 128; k++) {
        float w = Wout[k * 64 + c];
        s0 += sh[4*gg+0][k] * w;
        s1 += sh[4*gg+1][k] * w;
        s2 += sh[4*gg+2][k] * w;
        s3 += sh[4*gg+3][k] * w;
    }
    out[(size_t)(n0 + 4*gg + 0) * 64 + c] = s0;
    out[(size_t)(n0 + 4*gg + 1) * 64 + c] = s1;
    out[(size_t)(n0 + 4*gg + 2) * 64 + c] = s2;
    out[(size_t)(n0 + 4*gg + 3) * 64 + c] = s3;
}

// ---------------- launch ----------------
extern "C" void kernel_launch(void* const* d_in, const int* in_sizes, int n_in,
                              void* d_out, int out_size)
{
    const float* x        = (const float*)d_in[0];
    const int*   pe_index = (const int*)  d_in[1];
    const float* pe_val   = (const float*)d_in[2];
    const float* W_in     = (const float*)d_in[3];
    const float* b_in     = (const float*)d_in[4];
    const float* W1       = (const float*)d_in[5];
    const float* b1       = (const float*)d_in[6];
    const float* W2       = (const float*)d_in[7];
    const float* b2       = (const float*)d_in[8];
    const float* W_fin    = (const float*)d_in[9];
    const float* b_fin    = (const float*)d_in[10];
    const float* W_x      = (const float*)d_in[11];
    const float* b_x      = (const float*)d_in[12];
    const float* head_b   = (const float*)d_in[13];
    const float* W_out    = (const float*)d_in[14];
    const float* b_out    = (const float*)d_in[15];
    float* out = (float*)d_out;

    void *p_xh, *p_wV, *p_deg;
    cudaGetSymbolAddress(&p_xh,  g_xh4);
    cudaGetSymbolAddress(&p_wV,  g_wV);
    cudaGetSymbolAddress(&p_deg, g_deg);

    cudaFuncSetAttribute(edge_kernel, cudaFuncAttributeMaxDynamicSharedMemorySize,
                         SMEM_TOT);

    cudaMemsetAsync(p_wV,  0, (size_t)NN * 128 * sizeof(float));   // launch 0
    cudaMemsetAsync(p_deg, 0, (size_t)NN * sizeof(float));         // launch 1

    prep_kernel<<<26, 256>>>(W_in, W1, W2, W_fin);                 // launch 2
    xh_kernel<<<NN / 8, 128>>>(x, W_x, b_x, (float*)p_xh);         // launch 3
    deg_kernel<<<(NE + 1023) / 1024, 256>>>(pe_index, (float*)p_deg); // launch 4

    // launch 5 -> ncu -s 5 -c 1 profiles THIS kernel
    edge_kernel<<<NE / 128, 512, SMEM_TOT>>>(pe_index, pe_val,
        b_in, b1, b2, b_fin,
        (const float4*)p_xh, (float*)p_wV);

    out_kernel<<<NN / 16, 256>>>((const float*)p_wV, (const float*)p_deg,
                                 head_b, W_out, b_out, out);
}

// round 12
// speedup vs baseline: 1.1706x; 1.1706x over previous
#include <cuda_runtime.h>
#include <cuda_fp16.h>
#include <math.h>
#include <stdint.h>

#define NE  800000
#define NN  50000
#define HID 128

// ---------------- scratch (static device globals; no allocation) ----------------
__device__ float4 g_xh4[NN * 32];     // xh = x@W_x + b_x, [N,128] as float4
__device__ float  g_wV [NN * 128];    // scatter-add accumulator
__device__ float  g_deg[NN];          // degree accumulator
// fragment-linear fp16 B operands, uint4 = frags for n-tile pair {2p, 2p+1}
__device__ uint4  g_fWin[8 * 2 * 32];    // 8 KB  (K padded to 32, zeros past 24)
__device__ uint4  g_fW1 [8 * 8 * 32];    // 32 KB
__device__ uint4  g_fW2 [8 * 8 * 32];    // 32 KB
__device__ uint4  g_fWf [8 * 8 * 32];    // 32 KB

// ---------------- SMEM layout (edge kernel, dynamic) ----------------
#define OFF_A    0          // 32KB A tile: 128 rows x 128 fp16 (256B/row), XOR-swizzled
#define OFF_PE   32768      // 8KB  pe tile: 128 rows x 32 fp16 (64B/row)
#define OFF_B0   40960      // 32KB frag buffer 0
#define OFF_B1   73728      // 32KB frag buffer 1
#define OFF_BIAS 106496     // 2KB: 4 stages x 128 floats
#define OFF_IDX  108544     // 1KB: tgt[128], src[128]
#define SMEM_TOT 109568
// scores overlay: fp32 [128][128] over B0+B1 (64KB exactly)

// ---------------- helpers ----------------
__device__ __forceinline__ uint32_t packh2(float lo, float hi) {
    __half2 h = __floats2half2_rn(lo, hi);
    return *(uint32_t*)&h;
}
// GELU exact-erf via Abramowitz-Stegun 7.1.26 (|err|<=1.5e-7), branchless.
__device__ __forceinline__ float gelu_f(float x) {
    float th = 0.5f * x;
    float u  = th * x;                                    // t^2 = x^2/2
    float at = 0.7071067811865476f * fabsf(x);            // t >= 0
    float d  = fmaf(0.3275911f, at, 1.0f);
    float k;  asm("rcp.approx.f32 %0, %1;" : "=f"(k) : "f"(d));
    float p = fmaf(1.061405429f, k, -1.453152027f);
    p = fmaf(p, k, 1.421413741f);
    p = fmaf(p, k, -0.284496736f);
    p = fmaf(p, k, 0.254829592f);
    p = p * k;
    float s  = p * __expf(-u);                            // = 1 - erf(t)
    float ah = fabsf(th);
    return (th + ah) - ah * s;
}
__device__ __forceinline__ void red4(float* p, float a, float b, float c, float d) {
    asm volatile("red.global.add.v4.f32 [%0], {%1,%2,%3,%4};"
                 :: "l"(p), "f"(a), "f"(b), "f"(c), "f"(d) : "memory");
}
__device__ __forceinline__ void red1(float* p, float v) {
    asm volatile("red.global.add.f32 [%0], %1;" :: "l"(p), "f"(v) : "memory");
}
__device__ __forceinline__ uint32_t s2u(const void* p) {
    uint32_t a;
    asm("{ .reg .u64 t; cvta.to.shared.u64 t, %1; cvt.u32.u64 %0, t; }" : "=r"(a) : "l"(p));
    return a;
}
__device__ __forceinline__ void cp16(uint32_t s, const void* g) {
    asm volatile("cp.async.cg.shared.global [%0], [%1], 16;" :: "r"(s), "l"(g));
}
#define CP_COMMIT() asm volatile("cp.async.commit_group;")
#define CP_WAIT(n)  asm volatile("cp.async.wait_group %0;" :: "n"(n) : "memory")

__device__ __forceinline__ void mma16(float d[4], const uint32_t a[4],
                                      uint32_t b0, uint32_t b1) {
    asm volatile(
        "mma.sync.aligned.m16n8k16.row.col.f32.f16.f16.f32 "
        "{%0,%1,%2,%3},{%4,%5,%6,%7},{%8,%9},{%0,%1,%2,%3};"
        : "+f"(d[0]), "+f"(d[1]), "+f"(d[2]), "+f"(d[3])
        : "r"(a[0]), "r"(a[1]), "r"(a[2]), "r"(a[3]), "r"(b0), "r"(b1));
}
__device__ __forceinline__ void ldm4(uint32_t a[4], uint32_t saddr) {
    asm volatile("ldmatrix.sync.aligned.m8n8.x4.shared.b16 {%0,%1,%2,%3}, [%4];"
                 : "=r"(a[0]), "=r"(a[1]), "=r"(a[2]), "=r"(a[3]) : "r"(saddr));
}

// ---------------- weight prep: fragment-linear fp16 B arrays (uint4 pairs) ----------------
__global__ void __launch_bounds__(256)
prep_kernel(const float* __restrict__ W_in, const float* __restrict__ W1,
            const float* __restrict__ W2,   const float* __restrict__ Wf)
{
    int idx = blockIdx.x * 256 + threadIdx.x;
    if (idx < 512) {                          // Win: pg(8) x ks(2) x lane(32)
        int lane = idx & 31, ks = (idx >> 5) & 1, pg = idx >> 6;
        int k0 = ks * 16 + 2 * (lane & 3);
        int n0 = pg * 16 + (lane >> 2), n1 = n0 + 8;
        uint4 u;
        u.x = packh2(k0     < 24 ? W_in[k0 * 128 + n0]       : 0.f,
                     k0 + 1 < 24 ? W_in[(k0 + 1) * 128 + n0] : 0.f);
        u.y = packh2(k0 + 8 < 24 ? W_in[(k0 + 8) * 128 + n0] : 0.f,
                     k0 + 9 < 24 ? W_in[(k0 + 9) * 128 + n0] : 0.f);
        u.z = packh2(k0     < 24 ? W_in[k0 * 128 + n1]       : 0.f,
                     k0 + 1 < 24 ? W_in[(k0 + 1) * 128 + n1] : 0.f);
        u.w = packh2(k0 + 8 < 24 ? W_in[(k0 + 8) * 128 + n1] : 0.f,
                     k0 + 9 < 24 ? W_in[(k0 + 9) * 128 + n1] : 0.f);
        g_fWin[(pg * 2 + ks) * 32 + lane] = u;
    } else {
        int r = idx - 512;
        if (r >= 3 * 2048) return;
        int sel = r >> 11; r &= 2047;
        int lane = r & 31, ks = (r >> 5) & 7, pg = r >> 8;
        int k0 = ks * 16 + 2 * (lane & 3);
        int n0 = pg * 16 + (lane >> 2), n1 = n0 + 8;
        const float* W = (sel == 0) ? W1 : (sel == 1) ? W2 : Wf;
        uint4* F       = (sel == 0) ? g_fW1 : (sel == 1) ? g_fW2 : g_fWf;
        uint4 u;
        u.x = packh2(W[k0 * 128 + n0],       W[(k0 + 1) * 128 + n0]);
        u.y = packh2(W[(k0 + 8) * 128 + n0], W[(k0 + 9) * 128 + n0]);
        u.z = packh2(W[k0 * 128 + n1],       W[(k0 + 1) * 128 + n1]);
        u.w = packh2(W[(k0 + 8) * 128 + n1], W[(k0 + 9) * 128 + n1]);
        F[(pg * 8 + ks) * 32 + lane] = u;
    }
}

// ---------------- MMA stage: warp tile m32 x n64, ldmatrix A + uint4 B ----------------
// A tile: 256B/row, 16B chunk q at physical chunk q^(row&7).
template<int KS>
__device__ __forceinline__ void mma_stageA(
    float acc[2][8][4], uint32_t ra0, uint32_t ra1, int hi, int rs,
    const uint4* F, int nc, int lane)
{
#pragma unroll
    for (int ks = 0; ks < KS; ks++) {
        uint32_t a0[4], a1[4];
        uint32_t off = (uint32_t)(((2 * ks + hi) ^ rs) << 4);
        ldm4(a0, ra0 + off);
        ldm4(a1, ra1 + off);
#pragma unroll
        for (int p = 0; p < 4; p++) {
            uint4 b = F[((nc * 4 + p) * KS + ks) * 32 + lane];
            mma16(acc[0][2*p],   a0, b.x, b.y);
            mma16(acc[1][2*p],   a1, b.x, b.y);
            mma16(acc[0][2*p+1], a0, b.z, b.w);
            mma16(acc[1][2*p+1], a1, b.z, b.w);
        }
    }
}

// PE tile: 64B/row (4 chunks), chunk q at physical q^((row>>1)&3).
__device__ __forceinline__ void mma_stagePE(
    float acc[2][8][4], uint32_t rp0, uint32_t rp1, int hi, int swp,
    const uint4* __restrict__ FWin, int nc, int lane)
{
#pragma unroll
    for (int ks = 0; ks < 2; ks++) {
        uint32_t a0[4], a1[4];
        uint32_t off = (uint32_t)(((2 * ks + hi) ^ swp) << 4);
        ldm4(a0, rp0 + off);
        ldm4(a1, rp1 + off);
#pragma unroll
        for (int p = 0; p < 4; p++) {
            uint4 b = __ldg(&FWin[((nc * 4 + p) * 2 + ks) * 32 + lane]);
            mma16(acc[0][2*p],   a0, b.x, b.y);
            mma16(acc[1][2*p],   a1, b.x, b.y);
            mma16(acc[0][2*p+1], a0, b.z, b.w);
            mma16(acc[1][2*p+1], a1, b.z, b.w);
        }
    }
}

__device__ __forceinline__ void zero_acc(float acc[2][8][4]) {
#pragma unroll
    for (int mt = 0; mt < 2; mt++)
#pragma unroll
        for (int nt = 0; nt < 8; nt++)
#pragma unroll
            for (int i = 0; i < 4; i++) acc[mt][nt][i] = 0.f;
}

// MODE 0: gelu -> fp16 store to A; MODE 1: plain fp16 store to A
template<int MODE>
__device__ __forceinline__ void epilogueH(
    float acc[2][8][4], const float* bias, uint32_t* A32,
    int mbase, int nbase, int g, int t)
{
#pragma unroll
    for (int nt = 0; nt < 8; nt++) {
        int c = nbase + nt * 8 + 2 * t;
        float2 bb = *(const float2*)(bias + c);
        int c2 = c >> 1;
        int w  = (((c2 >> 2) ^ g) << 2) + (c2 & 3);
#pragma unroll
        for (int mt = 0; mt < 2; mt++) {
            int r0 = mbase + mt * 16 + g;
            float v0 = acc[mt][nt][0] + bb.x, v1 = acc[mt][nt][1] + bb.y;
            float v2 = acc[mt][nt][2] + bb.x, v3 = acc[mt][nt][3] + bb.y;
            if (MODE == 0) {
                v0 = gelu_f(v0); v1 = gelu_f(v1);
                v2 = gelu_f(v2); v3 = gelu_f(v3);
            }
            A32[r0 * 64 + w]       = packh2(v0, v1);
            A32[(r0 + 8) * 64 + w] = packh2(v2, v3);
        }
    }
}

// scores epilogue: fp32 into S with per-row 16B-chunk XOR swizzle
__device__ __forceinline__ void epilogueS(
    float acc[2][8][4], const float* bias, float* S,
    int mbase, int nbase, int g, int t)
{
#pragma unroll
    for (int nt = 0; nt < 8; nt++) {
        int c = nbase + nt * 8 + 2 * t;
        float2 bb = *(const float2*)(bias + c);
        int w = (((c >> 2) ^ g) << 2) + (c & 3);
#pragma unroll
        for (int mt = 0; mt < 2; mt++) {
            int r0 = mbase + mt * 16 + g;
            *(float2*)(S + r0 * 128 + w) =
                make_float2(acc[mt][nt][0] + bb.x, acc[mt][nt][1] + bb.y);
            *(float2*)(S + (r0 + 8) * 128 + w) =
                make_float2(acc[mt][nt][2] + bb.x, acc[mt][nt][3] + bb.y);
        }
    }
}

// ---------------- fused edge kernel (mma.sync fp16, 2 CTAs/SM) ----------------
__global__ void __launch_bounds__(256, 2)
edge_kernel(const int* __restrict__ pe_index, const float* __restrict__ pe_val,
            const float* __restrict__ b_in, const float* __restrict__ b1,
            const float* __restrict__ b2,   const float* __restrict__ bf,
            const float4* __restrict__ xh4,
            float* __restrict__ wV, float* __restrict__ deg)
{
    extern __shared__ char smem[];
    uint32_t sm = s2u(smem);
    uint32_t* A32   = (uint32_t*)(smem + OFF_A);
    uint32_t* PE32  = (uint32_t*)(smem + OFF_PE);
    const uint4* F0 = (const uint4*)(smem + OFF_B0);
    const uint4* F1 = (const uint4*)(smem + OFF_B1);
    float* sBias    = (float*)(smem + OFF_BIAS);
    int*   sIdx     = (int*)(smem + OFF_IDX);

    int tid  = threadIdx.x;
    int wid  = tid >> 5, lane = tid & 31;
    int mr   = wid & 3,  nc   = wid >> 2;
    int g    = lane >> 2, t   = lane & 3;
    int mbase = mr * 32, nbase = nc * 64;
    int e0   = blockIdx.x * 128;

    // ldmatrix per-lane bases (A row = 256 bytes, PE row = 64 bytes)
    int l15 = lane & 15, hi = lane >> 4, rs = lane & 7;
    int swp = (l15 >> 1) & 3;
    uint32_t ra0 = sm + OFF_A  + (uint32_t)(mbase + l15) * 256;
    uint32_t ra1 = ra0 + 16 * 256;
    uint32_t rp0 = sm + OFF_PE + (uint32_t)(mbase + l15) * 64;
    uint32_t rp1 = rp0 + 16 * 64;

    // --- stage W1 -> B0, W2 -> B1 via cp.async ---
#pragma unroll
    for (int i = 0; i < 8; i++)
        cp16(sm + OFF_B0 + (i * 256 + tid) * 16, (const char*)g_fW1 + (i * 256 + tid) * 16);
    CP_COMMIT();
#pragma unroll
    for (int i = 0; i < 8; i++)
        cp16(sm + OFF_B1 + (i * 256 + tid) * 16, (const char*)g_fW2 + (i * 256 + tid) * 16);
    CP_COMMIT();

    // --- indices + biases ---
    sIdx[tid] = (tid < 128) ? pe_index[e0 + tid] : pe_index[NE + e0 + (tid - 128)];
#pragma unroll
    for (int i = tid; i < 512; i += 256) {
        int st = i >> 7, c = i & 127;
        float v = (st == 0) ? b_in[c] : (st == 1) ? b1[c]
                : (st == 2) ? (b_in[c] + b2[c])   : bf[c];
        sBias[i] = v;
    }

    // --- build PE tile (fp16, K 24 padded to 32) ---
    {
        int row = tid >> 1, half = tid & 1;
        const float4* pr = (const float4*)(pe_val + (size_t)(e0 + row) * 24) + half * 4;
        uint32_t w[8];
        if (half == 0) {
            float4 v0 = pr[0], v1 = pr[1], v2 = pr[2], v3 = pr[3];
            w[0] = packh2(v0.x, v0.y); w[1] = packh2(v0.z, v0.w);
            w[2] = packh2(v1.x, v1.y); w[3] = packh2(v1.z, v1.w);
            w[4] = packh2(v2.x, v2.y); w[5] = packh2(v2.z, v2.w);
            w[6] = packh2(v3.x, v3.y); w[7] = packh2(v3.z, v3.w);
        } else {
            float4 v0 = pr[0], v1 = pr[1];
            w[0] = packh2(v0.x, v0.y); w[1] = packh2(v0.z, v0.w);
            w[2] = packh2(v1.x, v1.y); w[3] = packh2(v1.z, v1.w);
            w[4] = w[5] = w[6] = w[7] = 0u;
        }
        int sw = (row >> 1) & 3;
        uint32_t* base = PE32 + row * 16;
        int q0 = half * 2, q1 = half * 2 + 1;
        *(uint4*)(base + ((q0 ^ sw) << 2)) = make_uint4(w[0], w[1], w[2], w[3]);
        *(uint4*)(base + ((q1 ^ sw) << 2)) = make_uint4(w[4], w[5], w[6], w[7]);
    }

    float acc[2][8][4];
    __syncthreads();                                 // PE + bias + idx visible

    // ---- stage 1: acc = pe @ Win (Win frags from L2) ----
    zero_acc(acc);
    mma_stagePE(acc, rp0, rp1, hi, swp, g_fWin, nc, lane);
    epilogueH<0>(acc, sBias, A32, mbase, nbase, g, t);      // A = gelu(x0+b_in)
    CP_WAIT(1);                                              // W1 resident
    __syncthreads();

    // ---- stage 2: acc = A @ W1 ----
    zero_acc(acc);
    mma_stageA<8>(acc, ra0, ra1, hi, rs, F0, nc, lane);
    __syncthreads();                                         // B0+A reads done

    // prefetch Wf -> B0
#pragma unroll
    for (int i = 0; i < 8; i++)
        cp16(sm + OFF_B0 + (i * 256 + tid) * 16, (const char*)g_fWf + (i * 256 + tid) * 16);
    CP_COMMIT();

    epilogueH<0>(acc, sBias + 128, A32, mbase, nbase, g, t); // A = gelu(h+b1)
    CP_WAIT(1);                                              // W2 resident
    __syncthreads();

    // ---- stage 3: acc = A @ W2 + pe @ Win (K-concat residual) ----
    zero_acc(acc);
    mma_stageA<8>(acc, ra0, ra1, hi, rs, F1, nc, lane);
    mma_stagePE(acc, rp0, rp1, hi, swp, g_fWin, nc, lane);
    __syncthreads();                                         // A reads done
    epilogueH<1>(acc, sBias + 256, A32, mbase, nbase, g, t); // A = res
    CP_WAIT(0);                                              // Wf resident
    __syncthreads();

    // ---- stage 4: acc = A @ Wf ----
    zero_acc(acc);
    mma_stageA<8>(acc, ra0, ra1, hi, rs, F0, nc, lane);
    __syncthreads();                                         // B0 reads done
    float* S = (float*)(smem + OFF_B0);                      // scores overlay 64KB
    epilogueS(acc, sBias + 384, S, mbase, nbase, g, t);
    __syncthreads();

    // ---- scatter: msg = xh[src]*score -> wV[tgt], deg[tgt]++ ----
#pragma unroll 4
    for (int i = 0; i < 16; i++) {
        int e    = wid * 16 + i;
        int tgt  = sIdx[e];
        int srcn = sIdx[128 + e];
        float4 xv = xh4[(size_t)srcn * 32 + lane];
        float4 s4 = *(const float4*)(S + e * 128 + ((lane ^ (e & 7)) << 2));
        red4(wV + (size_t)tgt * 128 + lane * 4,
             xv.x * s4.x, xv.y * s4.y, xv.z * s4.z, xv.w * s4.w);
        if (lane == 0) red1(deg + tgt, 1.0f);
    }
}

// ---------------- node projection: xh = x @ W_x + b_x (8 nodes/block) ----------------
__global__ void __launch_bounds__(128)
xh_kernel(const float* __restrict__ x, const float* __restrict__ Wx,
          const float* __restrict__ bx, float* __restrict__ xh)
{
    __shared__ float sx[8][64];
    int tid = threadIdx.x;
    int n0  = blockIdx.x * 8;
#pragma unroll
    for (int i = tid; i < 512; i += 128)
        sx[i >> 6][i & 63] = x[(size_t)n0 * 64 + i];
    __syncthreads();
    int c = tid;
    float s[8];
#pragma unroll
    for (int j = 0; j < 8; j++) s[j] = bx[c];
#pragma unroll 8
    for (int k = 0; k < 64; k++) {
        float w = Wx[k * 128 + c];
#pragma unroll
        for (int j = 0; j < 8; j++) s[j] += sx[j][k] * w;
    }
#pragma unroll
    for (int j = 0; j < 8; j++)
        xh[(size_t)(n0 + j) * 128 + c] = s[j];
}

// ---------------- output projection (16 nodes/block, 4 nodes/thread) ----------------
__global__ void __launch_bounds__(256)
out_kernel(const float* __restrict__ wV, const float* __restrict__ deg,
           const float* __restrict__ hb, const float* __restrict__ Wout,
           const float* __restrict__ bout, float* __restrict__ out)
{
    __shared__ float sh[16][128];
    int tid = threadIdx.x;
    int n0  = blockIdx.x * 16;
#pragma unroll
    for (int i = tid; i < 2048; i += 256) {
        int nn = i >> 7, k = i & 127;
        int n  = n0 + nn;
        float d = deg[n];
        float invd = 1.0f / (d > 1.0f ? d : 1.0f);
        sh[nn][k] = wV[(size_t)n * 128 + k] * invd + hb[k];
    }
    __syncthreads();
    int gg = tid >> 6, c = tid & 63;
    float s0 = bout[c], s1 = s0, s2 = s0, s3 = s0;
#pragma unroll 8
    for (int k = 0; k < 128; k++) {
        float w = Wout[k * 64 + c];
        s0 += sh[4*gg+0][k] * w;
        s1 += sh[4*gg+1][k] * w;
        s2 += sh[4*gg+2][k] * w;
        s3 += sh[4*gg+3][k] * w;
    }
    out[(size_t)(n0 + 4*gg + 0) * 64 + c] = s0;
    out[(size_t)(n0 + 4*gg + 1) * 64 + c] = s1;
    out[(size_t)(n0 + 4*gg + 2) * 64 + c] = s2;
    out[(size_t)(n0 + 4*gg + 3) * 64 + c] = s3;
}

// ---------------- launch ----------------
extern "C" void kernel_launch(void* const* d_in, const int* in_sizes, int n_in,
                              void* d_out, int out_size)
{
    const float* x        = (const float*)d_in[0];
    const int*   pe_index = (const int*)  d_in[1];
    const float* pe_val   = (const float*)d_in[2];
    const float* W_in     = (const float*)d_in[3];
    const float* b_in     = (const float*)d_in[4];
    const float* W1       = (const float*)d_in[5];
    const float* b1       = (const float*)d_in[6];
    const float* W2       = (const float*)d_in[7];
    const float* b2       = (const float*)d_in[8];
    const float* W_fin    = (const float*)d_in[9];
    const float* b_fin    = (const float*)d_in[10];
    const float* W_x      = (const float*)d_in[11];
    const float* b_x      = (const float*)d_in[12];
    const float* head_b   = (const float*)d_in[13];
    const float* W_out    = (const float*)d_in[14];
    const float* b_out    = (const float*)d_in[15];
    float* out = (float*)d_out;

    void *p_xh, *p_wV, *p_deg;
    cudaGetSymbolAddress(&p_xh,  g_xh4);
    cudaGetSymbolAddress(&p_wV,  g_wV);
    cudaGetSymbolAddress(&p_deg, g_deg);

    cudaFuncSetAttribute(edge_kernel, cudaFuncAttributeMaxDynamicSharedMemorySize,
                         SMEM_TOT);

    const size_t half = (size_t)NN * 64 * sizeof(float);
    cudaMemsetAsync(p_wV, 0, half);                                  // launch 0
    cudaMemsetAsync((char*)p_wV + half, 0, half);                    // launch 1
    cudaMemsetAsync(p_deg, 0, (size_t)NN * sizeof(float));           // launch 2

    prep_kernel<<<26, 256>>>(W_in, W1, W2, W_fin);                   // launch 3
    xh_kernel<<<NN / 8, 128>>>(x, W_x, b_x, (float*)p_xh);           // launch 4

    // launch 5 -> ncu -s 5 -c 1 profiles THIS kernel
    edge_kernel<<<NE / 128, 256, SMEM_TOT>>>(pe_index, pe_val,
        b_in, b1, b2, b_fin,
        (const float4*)p_xh, (float*)p_wV, (float*)p_deg);

    out_kernel<<<NN / 16, 256>>>((const float*)p_wV, (const float*)p_deg,
                                 head_b, W_out, b_out, out);
}

// round 13
// speedup vs baseline: 1.3260x; 1.1328x over previous
#include <cuda_runtime.h>
#include <cuda_fp16.h>
#include <math.h>
#include <stdint.h>

#define NE  800000
#define NN  50000
#define HID 128

// ---------------- scratch (static device globals; no allocation) ----------------
__device__ float4 g_xh4[NN * 32];     // xh = x@W_x + b_x, [N,128] as float4
__device__ float  g_wV [NN * 128];    // scatter-add accumulator
__device__ float  g_deg[NN];          // degree accumulator
__device__ float  g_W2f [128 * 128];  // fp32 composed W2 @ Wf
__device__ float  g_Winf[32 * 128];   // fp32 composed Win @ Wf (rows 24..31 zero)
__device__ float  g_cbias[128];       // (b_in+b2) @ Wf + bf
// fragment-linear fp16 B operands, uint4 = frags for n-tile pair {2p, 2p+1}
__device__ uint4  g_fWin [8 * 2 * 32];   // 8 KB  (K padded to 32, zeros past 24)
__device__ uint4  g_fW1  [8 * 8 * 32];   // 32 KB
__device__ uint4  g_fW2f [8 * 8 * 32];   // 32 KB composed
__device__ uint4  g_fWinf[8 * 2 * 32];   // 8 KB composed

// ---------------- SMEM layout (edge kernel, dynamic) ----------------
#define OFF_A    0          // 32KB A tile: 128 rows x 128 fp16 (256B/row), XOR-swizzled
#define OFF_PE   32768      // 8KB  pe tile: 128 rows x 32 fp16 (64B/row)
#define OFF_B0   40960      // 32KB frag buffer 0 (W1)
#define OFF_B1   73728      // 32KB frag buffer 1 (W2f)
#define OFF_BIAS 106496     // 1.5KB: 3 stages x 128 floats
#define OFF_IDX  108544     // 1KB: tgt[128], src[128]
#define SMEM_TOT 109568
// scores overlay: fp32 [128][128] over B0+B1 (64KB exactly)

// ---------------- helpers ----------------
__device__ __forceinline__ uint32_t packh2(float lo, float hi) {
    __half2 h = __floats2half2_rn(lo, hi);
    return *(uint32_t*)&h;
}
// GELU exact-erf via Abramowitz-Stegun 7.1.26 (|err|<=1.5e-7), branchless.
__device__ __forceinline__ float gelu_f(float x) {
    float th = 0.5f * x;
    float u  = th * x;                                    // t^2 = x^2/2
    float at = 0.7071067811865476f * fabsf(x);            // t >= 0
    float d  = fmaf(0.3275911f, at, 1.0f);
    float k;  asm("rcp.approx.f32 %0, %1;" : "=f"(k) : "f"(d));
    float p = fmaf(1.061405429f, k, -1.453152027f);
    p = fmaf(p, k, 1.421413741f);
    p = fmaf(p, k, -0.284496736f);
    p = fmaf(p, k, 0.254829592f);
    p = p * k;
    float s  = p * __expf(-u);                            // = 1 - erf(t)
    float ah = fabsf(th);
    return (th + ah) - ah * s;
}
__device__ __forceinline__ void red4(float* p, float a, float b, float c, float d) {
    asm volatile("red.global.add.v4.f32 [%0], {%1,%2,%3,%4};"
                 :: "l"(p), "f"(a), "f"(b), "f"(c), "f"(d) : "memory");
}
__device__ __forceinline__ void red1(float* p, float v) {
    asm volatile("red.global.add.f32 [%0], %1;" :: "l"(p), "f"(v) : "memory");
}
__device__ __forceinline__ uint32_t s2u(const void* p) {
    uint32_t a;
    asm("{ .reg .u64 t; cvta.to.shared.u64 t, %1; cvt.u32.u64 %0, t; }" : "=r"(a) : "l"(p));
    return a;
}
__device__ __forceinline__ void cp16(uint32_t s, const void* g) {
    asm volatile("cp.async.cg.shared.global [%0], [%1], 16;" :: "r"(s), "l"(g));
}
#define CP_COMMIT() asm volatile("cp.async.commit_group;")
#define CP_WAIT(n)  asm volatile("cp.async.wait_group %0;" :: "n"(n) : "memory")

__device__ __forceinline__ void mma16(float d[4], const uint32_t a[4],
                                      uint32_t b0, uint32_t b1) {
    asm volatile(
        "mma.sync.aligned.m16n8k16.row.col.f32.f16.f16.f32 "
        "{%0,%1,%2,%3},{%4,%5,%6,%7},{%8,%9},{%0,%1,%2,%3};"
        : "+f"(d[0]), "+f"(d[1]), "+f"(d[2]), "+f"(d[3])
        : "r"(a[0]), "r"(a[1]), "r"(a[2]), "r"(a[3]), "r"(b0), "r"(b1));
}
__device__ __forceinline__ void ldm4(uint32_t a[4], uint32_t saddr) {
    asm volatile("ldmatrix.sync.aligned.m8n8.x4.shared.b16 {%0,%1,%2,%3}, [%4];"
                 : "=r"(a[0]), "=r"(a[1]), "=r"(a[2]), "=r"(a[3]) : "r"(saddr));
}

// ---------------- prep1: compose W2f = W2@Wf, Winf = Win@Wf, cbias ----------------
__global__ void __launch_bounds__(256)
prep1_kernel(const float* __restrict__ W_in, const float* __restrict__ b_in,
             const float* __restrict__ W2,   const float* __restrict__ b2,
             const float* __restrict__ Wf,   const float* __restrict__ bf)
{
    int idx = blockIdx.x * 256 + threadIdx.x;
    if (idx < 16384) {                         // W2f[k][n]
        int k = idx >> 7, n = idx & 127;
        float s = 0.f;
        for (int j = 0; j < 128; j++) s += W2[k * 128 + j] * Wf[j * 128 + n];
        g_W2f[idx] = s;
    } else if (idx < 16384 + 4096) {           // Winf[k][n], k<32 (zero past 23)
        int r = idx - 16384;
        int k = r >> 7, n = r & 127;
        float s = 0.f;
        if (k < 24)
            for (int j = 0; j < 128; j++) s += W_in[k * 128 + j] * Wf[j * 128 + n];
        g_Winf[r] = s;
    } else if (idx < 16384 + 4096 + 128) {     // cbias[n]
        int n = idx - (16384 + 4096);
        float s = bf[n];
        for (int j = 0; j < 128; j++) s += (b_in[j] + b2[j]) * Wf[j * 128 + n];
        g_cbias[n] = s;
    }
}

// ---------------- prep2: pack fragment-linear fp16 B arrays (uint4 pairs) ----------------
__global__ void __launch_bounds__(256)
prep2_kernel(const float* __restrict__ W_in, const float* __restrict__ W1)
{
    int idx = blockIdx.x * 256 + threadIdx.x;
    if (idx < 512) {                           // fWin from W_in (K=24 guard)
        int lane = idx & 31, ks = (idx >> 5) & 1, pg = idx >> 6;
        int k0 = ks * 16 + 2 * (lane & 3);
        int n0 = pg * 16 + (lane >> 2), n1 = n0 + 8;
        uint4 u;
        u.x = packh2(k0     < 24 ? W_in[k0 * 128 + n0]       : 0.f,
                     k0 + 1 < 24 ? W_in[(k0 + 1) * 128 + n0] : 0.f);
        u.y = packh2(k0 + 8 < 24 ? W_in[(k0 + 8) * 128 + n0] : 0.f,
                     k0 + 9 < 24 ? W_in[(k0 + 9) * 128 + n0] : 0.f);
        u.z = packh2(k0     < 24 ? W_in[k0 * 128 + n1]       : 0.f,
                     k0 + 1 < 24 ? W_in[(k0 + 1) * 128 + n1] : 0.f);
        u.w = packh2(k0 + 8 < 24 ? W_in[(k0 + 8) * 128 + n1] : 0.f,
                     k0 + 9 < 24 ? W_in[(k0 + 9) * 128 + n1] : 0.f);
        g_fWin[(pg * 2 + ks) * 32 + lane] = u;
    } else if (idx < 512 + 2048) {             // fW1 from W1
        int r = idx - 512;
        int lane = r & 31, ks = (r >> 5) & 7, pg = r >> 8;
        int k0 = ks * 16 + 2 * (lane & 3);
        int n0 = pg * 16 + (lane >> 2), n1 = n0 + 8;
        uint4 u;
        u.x = packh2(W1[k0 * 128 + n0],       W1[(k0 + 1) * 128 + n0]);
        u.y = packh2(W1[(k0 + 8) * 128 + n0], W1[(k0 + 9) * 128 + n0]);
        u.z = packh2(W1[k0 * 128 + n1],       W1[(k0 + 1) * 128 + n1]);
        u.w = packh2(W1[(k0 + 8) * 128 + n1], W1[(k0 + 9) * 128 + n1]);
        g_fW1[(pg * 8 + ks) * 32 + lane] = u;
    } else if (idx < 512 + 2048 + 2048) {      // fW2f from g_W2f
        int r = idx - (512 + 2048);
        int lane = r & 31, ks = (r >> 5) & 7, pg = r >> 8;
        int k0 = ks * 16 + 2 * (lane & 3);
        int n0 = pg * 16 + (lane >> 2), n1 = n0 + 8;
        uint4 u;
        u.x = packh2(g_W2f[k0 * 128 + n0],       g_W2f[(k0 + 1) * 128 + n0]);
        u.y = packh2(g_W2f[(k0 + 8) * 128 + n0], g_W2f[(k0 + 9) * 128 + n0]);
        u.z = packh2(g_W2f[k0 * 128 + n1],       g_W2f[(k0 + 1) * 128 + n1]);
        u.w = packh2(g_W2f[(k0 + 8) * 128 + n1], g_W2f[(k0 + 9) * 128 + n1]);
        g_fW2f[(pg * 8 + ks) * 32 + lane] = u;
    } else if (idx < 512 + 2048 + 2048 + 512) { // fWinf from g_Winf (32 rows, pre-zeroed)
        int r = idx - (512 + 2048 + 2048);
        int lane = r & 31, ks = (r >> 5) & 1, pg = r >> 6;
        int k0 = ks * 16 + 2 * (lane & 3);
        int n0 = pg * 16 + (lane >> 2), n1 = n0 + 8;
        uint4 u;
        u.x = packh2(g_Winf[k0 * 128 + n0],       g_Winf[(k0 + 1) * 128 + n0]);
        u.y = packh2(g_Winf[(k0 + 8) * 128 + n0], g_Winf[(k0 + 9) * 128 + n0]);
        u.z = packh2(g_Winf[k0 * 128 + n1],       g_Winf[(k0 + 1) * 128 + n1]);
        u.w = packh2(g_Winf[(k0 + 8) * 128 + n1], g_Winf[(k0 + 9) * 128 + n1]);
        g_fWinf[(pg * 2 + ks) * 32 + lane] = u;
    }
}

// ---------------- MMA stage: warp tile m32 x n64, ldmatrix A + uint4 B ----------------
// A tile: 256B/row, 16B chunk q at physical chunk q^(row&7).
template<int KS>
__device__ __forceinline__ void mma_stageA(
    float acc[2][8][4], uint32_t ra0, uint32_t ra1, int hi, int rs,
    const uint4* F, int nc, int lane)
{
#pragma unroll
    for (int ks = 0; ks < KS; ks++) {
        uint32_t a0[4], a1[4];
        uint32_t off = (uint32_t)(((2 * ks + hi) ^ rs) << 4);
        ldm4(a0, ra0 + off);
        ldm4(a1, ra1 + off);
#pragma unroll
        for (int p = 0; p < 4; p++) {
            uint4 b = F[((nc * 4 + p) * KS + ks) * 32 + lane];
            mma16(acc[0][2*p],   a0, b.x, b.y);
            mma16(acc[1][2*p],   a1, b.x, b.y);
            mma16(acc[0][2*p+1], a0, b.z, b.w);
            mma16(acc[1][2*p+1], a1, b.z, b.w);
        }
    }
}

// PE tile: 64B/row (4 chunks), chunk q at physical q^((row>>1)&3). B frags via __ldg.
__device__ __forceinline__ void mma_stagePE(
    float acc[2][8][4], uint32_t rp0, uint32_t rp1, int hi, int swp,
    const uint4* __restrict__ F, int nc, int lane)
{
#pragma unroll
    for (int ks = 0; ks < 2; ks++) {
        uint32_t a0[4], a1[4];
        uint32_t off = (uint32_t)(((2 * ks + hi) ^ swp) << 4);
        ldm4(a0, rp0 + off);
        ldm4(a1, rp1 + off);
#pragma unroll
        for (int p = 0; p < 4; p++) {
            uint4 b = __ldg(&F[((nc * 4 + p) * 2 + ks) * 32 + lane]);
            mma16(acc[0][2*p],   a0, b.x, b.y);
            mma16(acc[1][2*p],   a1, b.x, b.y);
            mma16(acc[0][2*p+1], a0, b.z, b.w);
            mma16(acc[1][2*p+1], a1, b.z, b.w);
        }
    }
}

__device__ __forceinline__ void zero_acc(float acc[2][8][4]) {
#pragma unroll
    for (int mt = 0; mt < 2; mt++)
#pragma unroll
        for (int nt = 0; nt < 8; nt++)
#pragma unroll
            for (int i = 0; i < 4; i++) acc[mt][nt][i] = 0.f;
}

// gelu -> fp16 store to A
__device__ __forceinline__ void epilogueH(
    float acc[2][8][4], const float* bias, uint32_t* A32,
    int mbase, int nbase, int g, int t)
{
#pragma unroll
    for (int nt = 0; nt < 8; nt++) {
        int c = nbase + nt * 8 + 2 * t;
        float2 bb = *(const float2*)(bias + c);
        int c2 = c >> 1;
        int w  = (((c2 >> 2) ^ g) << 2) + (c2 & 3);
#pragma unroll
        for (int mt = 0; mt < 2; mt++) {
            int r0 = mbase + mt * 16 + g;
            float v0 = gelu_f(acc[mt][nt][0] + bb.x);
            float v1 = gelu_f(acc[mt][nt][1] + bb.y);
            float v2 = gelu_f(acc[mt][nt][2] + bb.x);
            float v3 = gelu_f(acc[mt][nt][3] + bb.y);
            A32[r0 * 64 + w]       = packh2(v0, v1);
            A32[(r0 + 8) * 64 + w] = packh2(v2, v3);
        }
    }
}

// scores epilogue: fp32 into S with per-row 16B-chunk XOR swizzle
__device__ __forceinline__ void epilogueS(
    float acc[2][8][4], const float* bias, float* S,
    int mbase, int nbase, int g, int t)
{
#pragma unroll
    for (int nt = 0; nt < 8; nt++) {
        int c = nbase + nt * 8 + 2 * t;
        float2 bb = *(const float2*)(bias + c);
        int w = (((c >> 2) ^ g) << 2) + (c & 3);
#pragma unroll
        for (int mt = 0; mt < 2; mt++) {
            int r0 = mbase + mt * 16 + g;
            *(float2*)(S + r0 * 128 + w) =
                make_float2(acc[mt][nt][0] + bb.x, acc[mt][nt][1] + bb.y);
            *(float2*)(S + (r0 + 8) * 128 + w) =
                make_float2(acc[mt][nt][2] + bb.x, acc[mt][nt][3] + bb.y);
        }
    }
}

// ---------------- fused edge kernel (mma.sync fp16, 3 stages, 2 CTAs/SM) ----------------
__global__ void __launch_bounds__(256, 2)
edge_kernel(const int* __restrict__ pe_index, const float* __restrict__ pe_val,
            const float* __restrict__ b_in, const float* __restrict__ b1,
            const float4* __restrict__ xh4,
            float* __restrict__ wV, float* __restrict__ deg)
{
    extern __shared__ char smem[];
    uint32_t sm = s2u(smem);
    uint32_t* A32   = (uint32_t*)(smem + OFF_A);
    uint32_t* PE32  = (uint32_t*)(smem + OFF_PE);
    const uint4* F0 = (const uint4*)(smem + OFF_B0);
    const uint4* F1 = (const uint4*)(smem + OFF_B1);
    float* sBias    = (float*)(smem + OFF_BIAS);
    int*   sIdx     = (int*)(smem + OFF_IDX);

    int tid  = threadIdx.x;
    int wid  = tid >> 5, lane = tid & 31;
    int mr   = wid & 3,  nc   = wid >> 2;
    int g    = lane >> 2, t   = lane & 3;
    int mbase = mr * 32, nbase = nc * 64;
    int e0   = blockIdx.x * 128;

    // ldmatrix per-lane bases (A row = 256 bytes, PE row = 64 bytes)
    int l15 = lane & 15, hi = lane >> 4, rs = lane & 7;
    int swp = (l15 >> 1) & 3;
    uint32_t ra0 = sm + OFF_A  + (uint32_t)(mbase + l15) * 256;
    uint32_t ra1 = ra0 + 16 * 256;
    uint32_t rp0 = sm + OFF_PE + (uint32_t)(mbase + l15) * 64;
    uint32_t rp1 = rp0 + 16 * 64;

    // --- stage W1 -> B0, W2f -> B1 via cp.async ---
#pragma unroll
    for (int i = 0; i < 8; i++)
        cp16(sm + OFF_B0 + (i * 256 + tid) * 16, (const char*)g_fW1 + (i * 256 + tid) * 16);
    CP_COMMIT();
#pragma unroll
    for (int i = 0; i < 8; i++)
        cp16(sm + OFF_B1 + (i * 256 + tid) * 16, (const char*)g_fW2f + (i * 256 + tid) * 16);
    CP_COMMIT();

    // --- indices + biases (3 stages: b_in, b1, cbias) ---
    sIdx[tid] = (tid < 128) ? pe_index[e0 + tid] : pe_index[NE + e0 + (tid - 128)];
    {
        int c = tid & 127;
        if (tid < 128)      sBias[tid] = b_in[c];
        else                sBias[tid] = b1[c];
        if (tid < 128)      sBias[256 + tid] = g_cbias[tid];
    }

    // --- build PE tile (fp16, K 24 padded to 32) ---
    {
        int row = tid >> 1, half = tid & 1;
        const float4* pr = (const float4*)(pe_val + (size_t)(e0 + row) * 24) + half * 4;
        uint32_t w[8];
        if (half == 0) {
            float4 v0 = pr[0], v1 = pr[1], v2 = pr[2], v3 = pr[3];
            w[0] = packh2(v0.x, v0.y); w[1] = packh2(v0.z, v0.w);
            w[2] = packh2(v1.x, v1.y); w[3] = packh2(v1.z, v1.w);
            w[4] = packh2(v2.x, v2.y); w[5] = packh2(v2.z, v2.w);
            w[6] = packh2(v3.x, v3.y); w[7] = packh2(v3.z, v3.w);
        } else {
            float4 v0 = pr[0], v1 = pr[1];
            w[0] = packh2(v0.x, v0.y); w[1] = packh2(v0.z, v0.w);
            w[2] = packh2(v1.x, v1.y); w[3] = packh2(v1.z, v1.w);
            w[4] = w[5] = w[6] = w[7] = 0u;
        }
        int sw = (row >> 1) & 3;
        uint32_t* base = PE32 + row * 16;
        int q0 = half * 2, q1 = half * 2 + 1;
        *(uint4*)(base + ((q0 ^ sw) << 2)) = make_uint4(w[0], w[1], w[2], w[3]);
        *(uint4*)(base + ((q1 ^ sw) << 2)) = make_uint4(w[4], w[5], w[6], w[7]);
    }

    float acc[2][8][4];
    __syncthreads();                                 // PE + bias + idx visible

    // ---- stage 1: acc = pe @ Win; A = gelu(acc + b_in) ----
    zero_acc(acc);
    mma_stagePE(acc, rp0, rp1, hi, swp, g_fWin, nc, lane);
    epilogueH(acc, sBias, A32, mbase, nbase, g, t);
    CP_WAIT(1);                                              // W1 resident
    __syncthreads();

    // ---- stage 2: acc = A @ W1; A = gelu(acc + b1) ----
    zero_acc(acc);
    mma_stageA<8>(acc, ra0, ra1, hi, rs, F0, nc, lane);
    __syncthreads();                                         // A reads done before overwrite
    epilogueH(acc, sBias + 128, A32, mbase, nbase, g, t);
    CP_WAIT(0);                                              // W2f resident
    __syncthreads();

    // ---- stage 3 (composed): score = A @ W2f + pe @ Winf + cbias ----
    zero_acc(acc);
    mma_stageA<8>(acc, ra0, ra1, hi, rs, F1, nc, lane);
    mma_stagePE(acc, rp0, rp1, hi, swp, g_fWinf, nc, lane);
    __syncthreads();                                         // B0/B1 reads done
    float* S = (float*)(smem + OFF_B0);                      // scores overlay 64KB
    epilogueS(acc, sBias + 256, S, mbase, nbase, g, t);
    __syncthreads();

    // ---- scatter: msg = xh[src]*score -> wV[tgt], deg[tgt]++ ----
#pragma unroll 4
    for (int i = 0; i < 16; i++) {
        int e    = wid * 16 + i;
        int tgt  = sIdx[e];
        int srcn = sIdx[128 + e];
        float4 xv = xh4[(size_t)srcn * 32 + lane];
        float4 s4 = *(const float4*)(S + e * 128 + ((lane ^ (e & 7)) << 2));
        red4(wV + (size_t)tgt * 128 + lane * 4,
             xv.x * s4.x, xv.y * s4.y, xv.z * s4.z, xv.w * s4.w);
        if (lane == 0) red1(deg + tgt, 1.0f);
    }
}

// ---------------- node projection: xh = x @ W_x + b_x (8 nodes/block) ----------------
__global__ void __launch_bounds__(128)
xh_kernel(const float* __restrict__ x, const float* __restrict__ Wx,
          const float* __restrict__ bx, float* __restrict__ xh)
{
    __shared__ float sx[8][64];
    int tid = threadIdx.x;
    int n0  = blockIdx.x * 8;
#pragma unroll
    for (int i = tid; i < 512; i += 128)
        sx[i >> 6][i & 63] = x[(size_t)n0 * 64 + i];
    __syncthreads();
    int c = tid;
    float s[8];
#pragma unroll
    for (int j = 0; j < 8; j++) s[j] = bx[c];
#pragma unroll 8
    for (int k = 0; k < 64; k++) {
        float w = Wx[k * 128 + c];
#pragma unroll
        for (int j = 0; j < 8; j++) s[j] += sx[j][k] * w;
    }
#pragma unroll
    for (int j = 0; j < 8; j++)
        xh[(size_t)(n0 + j) * 128 + c] = s[j];
}

// ---------------- output projection (16 nodes/block, 4 nodes/thread) ----------------
__global__ void __launch_bounds__(256)
out_kernel(const float* __restrict__ wV, const float* __restrict__ deg,
           const float* __restrict__ hb, const float* __restrict__ Wout,
           const float* __restrict__ bout, float* __restrict__ out)
{
    __shared__ float sh[16][128];
    int tid = threadIdx.x;
    int n0  = blockIdx.x * 16;
#pragma unroll
    for (int i = tid; i < 2048; i += 256) {
        int nn = i >> 7, k = i & 127;
        int n  = n0 + nn;
        float d = deg[n];
        float invd = 1.0f / (d > 1.0f ? d : 1.0f);
        sh[nn][k] = wV[(size_t)n * 128 + k] * invd + hb[k];
    }
    __syncthreads();
    int gg = tid >> 6, c = tid & 63;
    float s0 = bout[c], s1 = s0, s2 = s0, s3 = s0;
#pragma unroll 8
    for (int k = 0; k < 128; k++) {
        float w = Wout[k * 64 + c];
        s0 += sh[4*gg+0][k] * w;
        s1 += sh[4*gg+1][k] * w;
        s2 += sh[4*gg+2][k] * w;
        s3 += sh[4*gg+3][k] * w;
    }
    out[(size_t)(n0 + 4*gg + 0) * 64 + c] = s0;
    out[(size_t)(n0 + 4*gg + 1) * 64 + c] = s1;
    out[(size_t)(n0 + 4*gg + 2) * 64 + c] = s2;
    out[(size_t)(n0 + 4*gg + 3) * 64 + c] = s3;
}

// ---------------- launch ----------------
extern "C" void kernel_launch(void* const* d_in, const int* in_sizes, int n_in,
                              void* d_out, int out_size)
{
    const float* x        = (const float*)d_in[0];
    const int*   pe_index = (const int*)  d_in[1];
    const float* pe_val   = (const float*)d_in[2];
    const float* W_in     = (const float*)d_in[3];
    const float* b_in     = (const float*)d_in[4];
    const float* W1       = (const float*)d_in[5];
    const float* b1       = (const float*)d_in[6];
    const float* W2       = (const float*)d_in[7];
    const float* b2       = (const float*)d_in[8];
    const float* W_fin    = (const float*)d_in[9];
    const float* b_fin    = (const float*)d_in[10];
    const float* W_x      = (const float*)d_in[11];
    const float* b_x      = (const float*)d_in[12];
    const float* head_b   = (const float*)d_in[13];
    const float* W_out    = (const float*)d_in[14];
    const float* b_out    = (const float*)d_in[15];
    float* out = (float*)d_out;

    void *p_xh, *p_wV, *p_deg;
    cudaGetSymbolAddress(&p_xh,  g_xh4);
    cudaGetSymbolAddress(&p_wV,  g_wV);
    cudaGetSymbolAddress(&p_deg, g_deg);

    cudaFuncSetAttribute(edge_kernel, cudaFuncAttributeMaxDynamicSharedMemorySize,
                         SMEM_TOT);

    cudaMemsetAsync(p_wV,  0, (size_t)NN * 128 * sizeof(float));
    cudaMemsetAsync(p_deg, 0, (size_t)NN * sizeof(float));

    prep1_kernel<<<81, 256>>>(W_in, b_in, W2, b2, W_fin, b_fin);
    prep2_kernel<<<20, 256>>>(W_in, W1);
    xh_kernel<<<NN / 8, 128>>>(x, W_x, b_x, (float*)p_xh);

    edge_kernel<<<NE / 128, 256, SMEM_TOT>>>(pe_index, pe_val,
        b_in, b1,
        (const float4*)p_xh, (float*)p_wV, (float*)p_deg);

    out_kernel<<<NN / 16, 256>>>((const float*)p_wV, (const float*)p_deg,
                                 head_b, W_out, b_out, out);
}

// round 14
// speedup vs baseline: 1.3279x; 1.0014x over previous
#include <cuda_runtime.h>
#include <cuda_fp16.h>
#include <math.h>
#include <stdint.h>

#define NE  800000
#define NN  50000
#define HID 128

// ---------------- scratch (static device globals; no allocation) ----------------
__device__ float4 g_xh4[NN * 32];     // xh = x@W_x + b_x, [N,128] as float4
__device__ float  g_wV [NN * 128];    // scatter-add accumulator
__device__ float  g_deg[NN];          // degree accumulator
__device__ float  g_W2f [128 * 128];  // fp32 composed W2 @ Wf
__device__ float  g_Winf[32 * 128];   // fp32 composed Win @ Wf (rows 24..31 zero)
__device__ float  g_cbias[128];       // (b_in+b2) @ Wf + bf
// fragment-linear fp16 B operands, uint4 = frags for n-tile pair {2p, 2p+1}
__device__ uint4  g_fWin [8 * 2 * 32];   // 8 KB  (K padded to 32, zeros past 24)
__device__ uint4  g_fW1  [8 * 8 * 32];   // 32 KB
__device__ uint4  g_fW2f [8 * 8 * 32];   // 32 KB composed
__device__ uint4  g_fWinf[8 * 2 * 32];   // 8 KB composed

// ---------------- SMEM layout (edge kernel, dynamic) ----------------
#define OFF_A    0          // 32KB A tile: 128 rows x 128 fp16 (256B/row), XOR-swizzled
#define OFF_PE   32768      // 8KB  pe tile: 128 rows x 32 fp16 (64B/row)
#define OFF_B0   40960      // 32KB frag buffer 0 (W1)
#define OFF_B1   73728      // 32KB frag buffer 1 (W2f)
#define OFF_BIAS 106496     // 1.5KB: 3 stages x 128 floats
#define OFF_IDX  108544     // 1KB: tgt[128], src[128]
#define SMEM_TOT 109568
// scores overlay: fp32 [128][128] over B0+B1 (64KB exactly)

// ---------------- helpers ----------------
__device__ __forceinline__ uint32_t packh2(float lo, float hi) {
    __half2 h = __floats2half2_rn(lo, hi);
    return *(uint32_t*)&h;
}
// GELU exact-erf via Abramowitz-Stegun 7.1.26 (|err|<=1.5e-7), branchless.
__device__ __forceinline__ float gelu_f(float x) {
    float th = 0.5f * x;
    float u  = th * x;                                    // t^2 = x^2/2
    float at = 0.7071067811865476f * fabsf(x);            // t >= 0
    float d  = fmaf(0.3275911f, at, 1.0f);
    float k;  asm("rcp.approx.f32 %0, %1;" : "=f"(k) : "f"(d));
    float p = fmaf(1.061405429f, k, -1.453152027f);
    p = fmaf(p, k, 1.421413741f);
    p = fmaf(p, k, -0.284496736f);
    p = fmaf(p, k, 0.254829592f);
    p = p * k;
    float s  = p * __expf(-u);                            // = 1 - erf(t)
    float ah = fabsf(th);
    return (th + ah) - ah * s;
}
__device__ __forceinline__ void red4(float* p, float a, float b, float c, float d) {
    asm volatile("red.global.add.v4.f32 [%0], {%1,%2,%3,%4};"
                 :: "l"(p), "f"(a), "f"(b), "f"(c), "f"(d) : "memory");
}
__device__ __forceinline__ void red1(float* p, float v) {
    asm volatile("red.global.add.f32 [%0], %1;" :: "l"(p), "f"(v) : "memory");
}
__device__ __forceinline__ uint32_t s2u(const void* p) {
    uint32_t a;
    asm("{ .reg .u64 t; cvta.to.shared.u64 t, %1; cvt.u32.u64 %0, t; }" : "=r"(a) : "l"(p));
    return a;
}
__device__ __forceinline__ void cp16(uint32_t s, const void* g) {
    asm volatile("cp.async.cg.shared.global [%0], [%1], 16;" :: "r"(s), "l"(g));
}
#define CP_COMMIT() asm volatile("cp.async.commit_group;")
#define CP_WAIT(n)  asm volatile("cp.async.wait_group %0;" :: "n"(n) : "memory")

__device__ __forceinline__ void mma16(float d[4], const uint32_t a[4],
                                      uint32_t b0, uint32_t b1) {
    asm volatile(
        "mma.sync.aligned.m16n8k16.row.col.f32.f16.f16.f32 "
        "{%0,%1,%2,%3},{%4,%5,%6,%7},{%8,%9},{%0,%1,%2,%3};"
        : "+f"(d[0]), "+f"(d[1]), "+f"(d[2]), "+f"(d[3])
        : "r"(a[0]), "r"(a[1]), "r"(a[2]), "r"(a[3]), "r"(b0), "r"(b1));
}
__device__ __forceinline__ void ldm4(uint32_t a[4], uint32_t saddr) {
    asm volatile("ldmatrix.sync.aligned.m8n8.x4.shared.b16 {%0,%1,%2,%3}, [%4];"
                 : "=r"(a[0]), "=r"(a[1]), "=r"(a[2]), "=r"(a[3]) : "r"(saddr));
}

// ---------------- prep1: compose W2f = W2@Wf, Winf = Win@Wf, cbias ----------------
__global__ void __launch_bounds__(256)
prep1_kernel(const float* __restrict__ W_in, const float* __restrict__ b_in,
             const float* __restrict__ W2,   const float* __restrict__ b2,
             const float* __restrict__ Wf,   const float* __restrict__ bf)
{
    int idx = blockIdx.x * 256 + threadIdx.x;
    if (idx < 16384) {                         // W2f[k][n]
        int k = idx >> 7, n = idx & 127;
        float s = 0.f;
        for (int j = 0; j < 128; j++) s += W2[k * 128 + j] * Wf[j * 128 + n];
        g_W2f[idx] = s;
    } else if (idx < 16384 + 4096) {           // Winf[k][n], k<32 (zero past 23)
        int r = idx - 16384;
        int k = r >> 7, n = r & 127;
        float s = 0.f;
        if (k < 24)
            for (int j = 0; j < 128; j++) s += W_in[k * 128 + j] * Wf[j * 128 + n];
        g_Winf[r] = s;
    } else if (idx < 16384 + 4096 + 128) {     // cbias[n]
        int n = idx - (16384 + 4096);
        float s = bf[n];
        for (int j = 0; j < 128; j++) s += (b_in[j] + b2[j]) * Wf[j * 128 + n];
        g_cbias[n] = s;
    }
}

// ---------------- prep2: pack fragment-linear fp16 B arrays (uint4 pairs) ----------------
__global__ void __launch_bounds__(256)
prep2_kernel(const float* __restrict__ W_in, const float* __restrict__ W1)
{
    int idx = blockIdx.x * 256 + threadIdx.x;
    if (idx < 512) {                           // fWin from W_in (K=24 guard)
        int lane = idx & 31, ks = (idx >> 5) & 1, pg = idx >> 6;
        int k0 = ks * 16 + 2 * (lane & 3);
        int n0 = pg * 16 + (lane >> 2), n1 = n0 + 8;
        uint4 u;
        u.x = packh2(k0     < 24 ? W_in[k0 * 128 + n0]       : 0.f,
                     k0 + 1 < 24 ? W_in[(k0 + 1) * 128 + n0] : 0.f);
        u.y = packh2(k0 + 8 < 24 ? W_in[(k0 + 8) * 128 + n0] : 0.f,
                     k0 + 9 < 24 ? W_in[(k0 + 9) * 128 + n0] : 0.f);
        u.z = packh2(k0     < 24 ? W_in[k0 * 128 + n1]       : 0.f,
                     k0 + 1 < 24 ? W_in[(k0 + 1) * 128 + n1] : 0.f);
        u.w = packh2(k0 + 8 < 24 ? W_in[(k0 + 8) * 128 + n1] : 0.f,
                     k0 + 9 < 24 ? W_in[(k0 + 9) * 128 + n1] : 0.f);
        g_fWin[(pg * 2 + ks) * 32 + lane] = u;
    } else if (idx < 512 + 2048) {             // fW1 from W1
        int r = idx - 512;
        int lane = r & 31, ks = (r >> 5) & 7, pg = r >> 8;
        int k0 = ks * 16 + 2 * (lane & 3);
        int n0 = pg * 16 + (lane >> 2), n1 = n0 + 8;
        uint4 u;
        u.x = packh2(W1[k0 * 128 + n0],       W1[(k0 + 1) * 128 + n0]);
        u.y = packh2(W1[(k0 + 8) * 128 + n0], W1[(k0 + 9) * 128 + n0]);
        u.z = packh2(W1[k0 * 128 + n1],       W1[(k0 + 1) * 128 + n1]);
        u.w = packh2(W1[(k0 + 8) * 128 + n1], W1[(k0 + 9) * 128 + n1]);
        g_fW1[(pg * 8 + ks) * 32 + lane] = u;
    } else if (idx < 512 + 2048 + 2048) {      // fW2f from g_W2f
        int r = idx - (512 + 2048);
        int lane = r & 31, ks = (r >> 5) & 7, pg = r >> 8;
        int k0 = ks * 16 + 2 * (lane & 3);
        int n0 = pg * 16 + (lane >> 2), n1 = n0 + 8;
        uint4 u;
        u.x = packh2(g_W2f[k0 * 128 + n0],       g_W2f[(k0 + 1) * 128 + n0]);
        u.y = packh2(g_W2f[(k0 + 8) * 128 + n0], g_W2f[(k0 + 9) * 128 + n0]);
        u.z = packh2(g_W2f[k0 * 128 + n1],       g_W2f[(k0 + 1) * 128 + n1]);
        u.w = packh2(g_W2f[(k0 + 8) * 128 + n1], g_W2f[(k0 + 9) * 128 + n1]);
        g_fW2f[(pg * 8 + ks) * 32 + lane] = u;
    } else if (idx < 512 + 2048 + 2048 + 512) { // fWinf from g_Winf (32 rows, pre-zeroed)
        int r = idx - (512 + 2048 + 2048);
        int lane = r & 31, ks = (r >> 5) & 1, pg = r >> 6;
        int k0 = ks * 16 + 2 * (lane & 3);
        int n0 = pg * 16 + (lane >> 2), n1 = n0 + 8;
        uint4 u;
        u.x = packh2(g_Winf[k0 * 128 + n0],       g_Winf[(k0 + 1) * 128 + n0]);
        u.y = packh2(g_Winf[(k0 + 8) * 128 + n0], g_Winf[(k0 + 9) * 128 + n0]);
        u.z = packh2(g_Winf[k0 * 128 + n1],       g_Winf[(k0 + 1) * 128 + n1]);
        u.w = packh2(g_Winf[(k0 + 8) * 128 + n1], g_Winf[(k0 + 9) * 128 + n1]);
        g_fWinf[(pg * 2 + ks) * 32 + lane] = u;
    }
}

// ---------------- MMA stage: warp tile m32 x n64, ldmatrix A + uint4 B ----------------
// A tile: 256B/row, 16B chunk q at physical chunk q^(row&7).
template<int KS>
__device__ __forceinline__ void mma_stageA(
    float acc[2][8][4], uint32_t ra0, uint32_t ra1, int hi, int rs,
    const uint4* F, int nc, int lane)
{
#pragma unroll
    for (int ks = 0; ks < KS; ks++) {
        uint32_t a0[4], a1[4];
        uint32_t off = (uint32_t)(((2 * ks + hi) ^ rs) << 4);
        ldm4(a0, ra0 + off);
        ldm4(a1, ra1 + off);
#pragma unroll
        for (int p = 0; p < 4; p++) {
            uint4 b = F[((nc * 4 + p) * KS + ks) * 32 + lane];
            mma16(acc[0][2*p],   a0, b.x, b.y);
            mma16(acc[1][2*p],   a1, b.x, b.y);
            mma16(acc[0][2*p+1], a0, b.z, b.w);
            mma16(acc[1][2*p+1], a1, b.z, b.w);
        }
    }
}

// PE tile: 64B/row (4 chunks), chunk q at physical q^((row>>1)&3). B frags via __ldg.
__device__ __forceinline__ void mma_stagePE(
    float acc[2][8][4], uint32_t rp0, uint32_t rp1, int hi, int swp,
    const uint4* __restrict__ F, int nc, int lane)
{
#pragma unroll
    for (int ks = 0; ks < 2; ks++) {
        uint32_t a0[4], a1[4];
        uint32_t off = (uint32_t)(((2 * ks + hi) ^ swp) << 4);
        ldm4(a0, rp0 + off);
        ldm4(a1, rp1 + off);
#pragma unroll
        for (int p = 0; p < 4; p++) {
            uint4 b = __ldg(&F[((nc * 4 + p) * 2 + ks) * 32 + lane]);
            mma16(acc[0][2*p],   a0, b.x, b.y);
            mma16(acc[1][2*p],   a1, b.x, b.y);
            mma16(acc[0][2*p+1], a0, b.z, b.w);
            mma16(acc[1][2*p+1], a1, b.z, b.w);
        }
    }
}

// init accumulators with the stage bias (replaces zeroing + epilogue bias add)
__device__ __forceinline__ void bias_acc(
    float acc[2][8][4], const float* bias, int nbase, int t)
{
#pragma unroll
    for (int nt = 0; nt < 8; nt++) {
        float2 bb = *(const float2*)(bias + nbase + nt * 8 + 2 * t);
#pragma unroll
        for (int mt = 0; mt < 2; mt++) {
            acc[mt][nt][0] = bb.x; acc[mt][nt][1] = bb.y;
            acc[mt][nt][2] = bb.x; acc[mt][nt][3] = bb.y;
        }
    }
}

// gelu -> fp16 store to A (bias already folded into acc)
__device__ __forceinline__ void epilogueH(
    float acc[2][8][4], uint32_t* A32, int mbase, int nbase, int g, int t)
{
#pragma unroll
    for (int nt = 0; nt < 8; nt++) {
        int c = nbase + nt * 8 + 2 * t;
        int c2 = c >> 1;
        int w  = (((c2 >> 2) ^ g) << 2) + (c2 & 3);
#pragma unroll
        for (int mt = 0; mt < 2; mt++) {
            int r0 = mbase + mt * 16 + g;
            float v0 = gelu_f(acc[mt][nt][0]);
            float v1 = gelu_f(acc[mt][nt][1]);
            float v2 = gelu_f(acc[mt][nt][2]);
            float v3 = gelu_f(acc[mt][nt][3]);
            A32[r0 * 64 + w]       = packh2(v0, v1);
            A32[(r0 + 8) * 64 + w] = packh2(v2, v3);
        }
    }
}

// scores epilogue: fp32 into S with per-row 16B-chunk XOR swizzle (bias in acc)
__device__ __forceinline__ void epilogueS(
    float acc[2][8][4], float* S, int mbase, int nbase, int g, int t)
{
#pragma unroll
    for (int nt = 0; nt < 8; nt++) {
        int c = nbase + nt * 8 + 2 * t;
        int w = (((c >> 2) ^ g) << 2) + (c & 3);
#pragma unroll
        for (int mt = 0; mt < 2; mt++) {
            int r0 = mbase + mt * 16 + g;
            *(float2*)(S + r0 * 128 + w) =
                make_float2(acc[mt][nt][0], acc[mt][nt][1]);
            *(float2*)(S + (r0 + 8) * 128 + w) =
                make_float2(acc[mt][nt][2], acc[mt][nt][3]);
        }
    }
}

// ---------------- fused edge kernel (mma.sync fp16, 3 stages, 2 CTAs/SM) ----------------
__global__ void __launch_bounds__(256, 2)
edge_kernel(const int* __restrict__ pe_index, const float* __restrict__ pe_val,
            const float* __restrict__ b_in, const float* __restrict__ b1,
            const float4* __restrict__ xh4,
            float* __restrict__ wV, float* __restrict__ deg)
{
    extern __shared__ char smem[];
    uint32_t sm = s2u(smem);
    uint32_t* A32   = (uint32_t*)(smem + OFF_A);
    uint32_t* PE32  = (uint32_t*)(smem + OFF_PE);
    const uint4* F0 = (const uint4*)(smem + OFF_B0);
    const uint4* F1 = (const uint4*)(smem + OFF_B1);
    float* sBias    = (float*)(smem + OFF_BIAS);
    int*   sIdx     = (int*)(smem + OFF_IDX);

    int tid  = threadIdx.x;
    int wid  = tid >> 5, lane = tid & 31;
    int mr   = wid & 3,  nc   = wid >> 2;
    int g    = lane >> 2, t   = lane & 3;
    int mbase = mr * 32, nbase = nc * 64;
    int e0   = blockIdx.x * 128;

    // ldmatrix per-lane bases (A row = 256 bytes, PE row = 64 bytes)
    int l15 = lane & 15, hi = lane >> 4, rs = lane & 7;
    int swp = (l15 >> 1) & 3;
    uint32_t ra0 = sm + OFF_A  + (uint32_t)(mbase + l15) * 256;
    uint32_t ra1 = ra0 + 16 * 256;
    uint32_t rp0 = sm + OFF_PE + (uint32_t)(mbase + l15) * 64;
    uint32_t rp1 = rp0 + 16 * 64;

    // --- stage W1 -> B0, W2f -> B1 via cp.async ---
#pragma unroll
    for (int i = 0; i < 8; i++)
        cp16(sm + OFF_B0 + (i * 256 + tid) * 16, (const char*)g_fW1 + (i * 256 + tid) * 16);
    CP_COMMIT();
#pragma unroll
    for (int i = 0; i < 8; i++)
        cp16(sm + OFF_B1 + (i * 256 + tid) * 16, (const char*)g_fW2f + (i * 256 + tid) * 16);
    CP_COMMIT();

    // --- indices + biases (3 stages: b_in, b1, cbias) ---
    sIdx[tid] = (tid < 128) ? pe_index[e0 + tid] : pe_index[NE + e0 + (tid - 128)];
    {
        int c = tid & 127;
        if (tid < 128)      sBias[tid] = b_in[c];
        else                sBias[tid] = b1[c];
        if (tid < 128)      sBias[256 + tid] = g_cbias[tid];
    }

    // --- build PE tile (fp16, K 24 padded to 32) ---
    {
        int row = tid >> 1, half = tid & 1;
        const float4* pr = (const float4*)(pe_val + (size_t)(e0 + row) * 24) + half * 4;
        uint32_t w[8];
        if (half == 0) {
            float4 v0 = pr[0], v1 = pr[1], v2 = pr[2], v3 = pr[3];
            w[0] = packh2(v0.x, v0.y); w[1] = packh2(v0.z, v0.w);
            w[2] = packh2(v1.x, v1.y); w[3] = packh2(v1.z, v1.w);
            w[4] = packh2(v2.x, v2.y); w[5] = packh2(v2.z, v2.w);
            w[6] = packh2(v3.x, v3.y); w[7] = packh2(v3.z, v3.w);
        } else {
            float4 v0 = pr[0], v1 = pr[1];
            w[0] = packh2(v0.x, v0.y); w[1] = packh2(v0.z, v0.w);
            w[2] = packh2(v1.x, v1.y); w[3] = packh2(v1.z, v1.w);
            w[4] = w[5] = w[6] = w[7] = 0u;
        }
        int sw = (row >> 1) & 3;
        uint32_t* base = PE32 + row * 16;
        int q0 = half * 2, q1 = half * 2 + 1;
        *(uint4*)(base + ((q0 ^ sw) << 2)) = make_uint4(w[0], w[1], w[2], w[3]);
        *(uint4*)(base + ((q1 ^ sw) << 2)) = make_uint4(w[4], w[5], w[6], w[7]);
    }

    float acc[2][8][4];
    __syncthreads();                                 // PE + bias + idx visible

    // early degree atomics: drain in background under the MMA stages
    if (lane == 0) {
#pragma unroll 4
        for (int i = 0; i < 16; i++)
            red1(deg + sIdx[wid * 16 + i], 1.0f);
    }

    // ---- stage 1: acc = b_in + pe @ Win; A = gelu(acc) ----
    bias_acc(acc, sBias, nbase, t);
    mma_stagePE(acc, rp0, rp1, hi, swp, g_fWin, nc, lane);
    epilogueH(acc, A32, mbase, nbase, g, t);
    CP_WAIT(1);                                              // W1 resident
    __syncthreads();

    // ---- stage 2: acc = b1 + A @ W1; A = gelu(acc) ----
    bias_acc(acc, sBias + 128, nbase, t);
    mma_stageA<8>(acc, ra0, ra1, hi, rs, F0, nc, lane);
    __syncthreads();                                         // A reads done before overwrite
    epilogueH(acc, A32, mbase, nbase, g, t);
    CP_WAIT(0);                                              // W2f resident
    __syncthreads();

    // ---- stage 3 (composed): score = cbias + A @ W2f + pe @ Winf ----
    bias_acc(acc, sBias + 256, nbase, t);
    mma_stageA<8>(acc, ra0, ra1, hi, rs, F1, nc, lane);
    mma_stagePE(acc, rp0, rp1, hi, swp, g_fWinf, nc, lane);
    __syncthreads();                                         // B0/B1 reads done
    float* S = (float*)(smem + OFF_B0);                      // scores overlay 64KB
    epilogueS(acc, S, mbase, nbase, g, t);
    __syncthreads();

    // ---- scatter: msg = xh[src]*score -> wV[tgt] ----
#pragma unroll 4
    for (int i = 0; i < 16; i++) {
        int e    = wid * 16 + i;
        int tgt  = sIdx[e];
        int srcn = sIdx[128 + e];
        float4 xv = xh4[(size_t)srcn * 32 + lane];
        float4 s4 = *(const float4*)(S + e * 128 + ((lane ^ (e & 7)) << 2));
        red4(wV + (size_t)tgt * 128 + lane * 4,
             xv.x * s4.x, xv.y * s4.y, xv.z * s4.z, xv.w * s4.w);
    }
}

// ---------------- node projection: xh = x @ W_x + b_x (8 nodes/block) ----------------
__global__ void __launch_bounds__(128)
xh_kernel(const float* __restrict__ x, const float* __restrict__ Wx,
          const float* __restrict__ bx, float* __restrict__ xh)
{
    __shared__ float sx[8][64];
    int tid = threadIdx.x;
    int n0  = blockIdx.x * 8;
#pragma unroll
    for (int i = tid; i < 512; i += 128)
        sx[i >> 6][i & 63] = x[(size_t)n0 * 64 + i];
    __syncthreads();
    int c = tid;
    float s[8];
#pragma unroll
    for (int j = 0; j < 8; j++) s[j] = bx[c];
#pragma unroll 8
    for (int k = 0; k < 64; k++) {
        float w = Wx[k * 128 + c];
#pragma unroll
        for (int j = 0; j < 8; j++) s[j] += sx[j][k] * w;
    }
#pragma unroll
    for (int j = 0; j < 8; j++)
        xh[(size_t)(n0 + j) * 128 + c] = s[j];
}

// ---------------- output projection (16 nodes/block, 4 nodes/thread) ----------------
__global__ void __launch_bounds__(256)
out_kernel(const float* __restrict__ wV, const float* __restrict__ deg,
           const float* __restrict__ hb, const float* __restrict__ Wout,
           const float* __restrict__ bout, float* __restrict__ out)
{
    __shared__ float sh[16][128];
    int tid = threadIdx.x;
    int n0  = blockIdx.x * 16;
#pragma unroll
    for (int i = tid; i < 2048; i += 256) {
        int nn = i >> 7, k = i & 127;
        int n  = n0 + nn;
        float d = deg[n];
        float invd = 1.0f / (d > 1.0f ? d : 1.0f);
        sh[nn][k] = wV[(size_t)n * 128 + k] * invd + hb[k];
    }
    __syncthreads();
    int gg = tid >> 6, c = tid & 63;
    float s0 = bout[c], s1 = s0, s2 = s0, s3 = s0;
#pragma unroll 8
    for (int k = 0; k < 128; k++) {
        float w = Wout[k * 64 + c];
        s0 += sh[4*gg+0][k] * w;
        s1 += sh[4*gg+1][k] * w;
        s2 += sh[4*gg+2][k] * w;
        s3 += sh[4*gg+3][k] * w;
    }
    out[(size_t)(n0 + 4*gg + 0) * 64 + c] = s0;
    out[(size_t)(n0 + 4*gg + 1) * 64 + c] = s1;
    out[(size_t)(n0 + 4*gg + 2) * 64 + c] = s2;
    out[(size_t)(n0 + 4*gg + 3) * 64 + c] = s3;
}

// ---------------- launch ----------------
extern "C" void kernel_launch(void* const* d_in, const int* in_sizes, int n_in,
                              void* d_out, int out_size)
{
    const float* x        = (const float*)d_in[0];
    const int*   pe_index = (const int*)  d_in[1];
    const float* pe_val   = (const float*)d_in[2];
    const float* W_in     = (const float*)d_in[3];
    const float* b_in     = (const float*)d_in[4];
    const float* W1       = (const float*)d_in[5];
    const float* b1       = (const float*)d_in[6];
    const float* W2       = (const float*)d_in[7];
    const float* b2       = (const float*)d_in[8];
    const float* W_fin    = (const float*)d_in[9];
    const float* b_fin    = (const float*)d_in[10];
    const float* W_x      = (const float*)d_in[11];
    const float* b_x      = (const float*)d_in[12];
    const float* head_b   = (const float*)d_in[13];
    const float* W_out    = (const float*)d_in[14];
    const float* b_out    = (const float*)d_in[15];
    float* out = (float*)d_out;

    void *p_xh, *p_wV, *p_deg;
    cudaGetSymbolAddress(&p_xh,  g_xh4);
    cudaGetSymbolAddress(&p_wV,  g_wV);
    cudaGetSymbolAddress(&p_deg, g_deg);

    cudaFuncSetAttribute(edge_kernel, cudaFuncAttributeMaxDynamicSharedMemorySize,
                         SMEM_TOT);

    cudaMemsetAsync(p_wV,  0, (size_t)NN * 128 * sizeof(float));
    cudaMemsetAsync(p_deg, 0, (size_t)NN * sizeof(float));

    prep1_kernel<<<81, 256>>>(W_in, b_in, W2, b2, W_fin, b_fin);
    prep2_kernel<<<20, 256>>>(W_in, W1);
    xh_kernel<<<NN / 8, 128>>>(x, W_x, b_x, (float*)p_xh);

    edge_kernel<<<NE / 128, 256, SMEM_TOT>>>(pe_index, pe_val,
        b_in, b1,
        (const float4*)p_xh, (float*)p_wV, (float*)p_deg);

    out_kernel<<<NN / 16, 256>>>((const float*)p_wV, (const float*)p_deg,
                                 head_b, W_out, b_out, out);
}

// round 15
// speedup vs baseline: 1.3789x; 1.0384x over previous
#include <cuda_runtime.h>
#include <cuda_fp16.h>
#include <math.h>
#include <stdint.h>

#define NE  800000
#define NN  50000
#define HID 128

// ---------------- scratch (static device globals; no allocation) ----------------
__device__ float4 g_xh4[NN * 32];     // xh = x@W_x + b_x, [N,128] as float4
__device__ float  g_wV [NN * 128];    // scatter-add accumulator
__device__ float  g_deg[NN];          // degree accumulator
__device__ float  g_W2f [128 * 128];  // fp32 composed W2 @ Wf
__device__ float  g_Winf[32 * 128];   // fp32 composed Win @ Wf (rows 24..31 zero)
__device__ float  g_cbias[128];       // (b_in+b2) @ Wf + bf
// fragment-linear fp16 B operands, uint4 = frags for n-tile pair {2p, 2p+1}
__device__ uint4  g_fWin [8 * 2 * 32];   // 8 KB  (K padded to 32, zeros past 24)
__device__ uint4  g_fW1  [8 * 8 * 32];   // 32 KB
__device__ uint4  g_fW2f [8 * 8 * 32];   // 32 KB composed
__device__ uint4  g_fWinf[8 * 2 * 32];   // 8 KB composed

// ---------------- SMEM layout (edge kernel, dynamic) ----------------
#define OFF_A    0          // 32KB A tile: 128 rows x 128 fp16 (256B/row), XOR-swizzled
#define OFF_PE   32768      // 8KB  pe tile: 128 rows x 32 fp16 (64B/row)
#define OFF_B0   40960      // 32KB frag buffer 0 (W1)
#define OFF_B1   73728      // 32KB frag buffer 1 (W2f)
#define OFF_BIAS 106496     // 1.5KB: 3 stages x 128 floats
#define OFF_IDX  108544     // 1KB: tgt<<9 [128], src<<9 [128]
#define SMEM_TOT 109568
// scores overlay: fp32 [128][128] over B0+B1 (64KB exactly)

// ---------------- helpers ----------------
__device__ __forceinline__ uint32_t packh2(float lo, float hi) {
    __half2 h = __floats2half2_rn(lo, hi);
    return *(uint32_t*)&h;
}
// GELU exact-erf via Abramowitz-Stegun 7.1.25 (3-term, |err|<=2.5e-5), branchless.
__device__ __forceinline__ float gelu_f(float x) {
    float th = 0.5f * x;
    float u  = th * x;                                    // t^2 = x^2/2
    float at = 0.7071067811865476f * fabsf(x);            // t >= 0
    float d  = fmaf(0.47047f, at, 1.0f);
    float k;  asm("rcp.approx.f32 %0, %1;" : "=f"(k) : "f"(d));
    float p = fmaf(0.7478556f, k, -0.0958798f);
    p = fmaf(p, k, 0.3480242f);
    p = p * k;
    float s  = p * __expf(-u);                            // = 1 - erf(t)
    float ah = fabsf(th);
    return (th + ah) - ah * s;
}
__device__ __forceinline__ void red4(float* p, float a, float b, float c, float d) {
    asm volatile("red.global.add.v4.f32 [%0], {%1,%2,%3,%4};"
                 :: "l"(p), "f"(a), "f"(b), "f"(c), "f"(d) : "memory");
}
__device__ __forceinline__ void red1(float* p, float v) {
    asm volatile("red.global.add.f32 [%0], %1;" :: "l"(p), "f"(v) : "memory");
}
__device__ __forceinline__ uint32_t s2u(const void* p) {
    uint32_t a;
    asm("{ .reg .u64 t; cvta.to.shared.u64 t, %1; cvt.u32.u64 %0, t; }" : "=r"(a) : "l"(p));
    return a;
}
__device__ __forceinline__ void cp16(uint32_t s, const void* g) {
    asm volatile("cp.async.cg.shared.global [%0], [%1], 16;" :: "r"(s), "l"(g));
}
#define CP_COMMIT() asm volatile("cp.async.commit_group;")
#define CP_WAIT(n)  asm volatile("cp.async.wait_group %0;" :: "n"(n) : "memory")

__device__ __forceinline__ void mma16(float d[4], const uint32_t a[4],
                                      uint32_t b0, uint32_t b1) {
    asm volatile(
        "mma.sync.aligned.m16n8k16.row.col.f32.f16.f16.f32 "
        "{%0,%1,%2,%3},{%4,%5,%6,%7},{%8,%9},{%0,%1,%2,%3};"
        : "+f"(d[0]), "+f"(d[1]), "+f"(d[2]), "+f"(d[3])
        : "r"(a[0]), "r"(a[1]), "r"(a[2]), "r"(a[3]), "r"(b0), "r"(b1));
}
__device__ __forceinline__ void ldm4(uint32_t a[4], uint32_t saddr) {
    asm volatile("ldmatrix.sync.aligned.m8n8.x4.shared.b16 {%0,%1,%2,%3}, [%4];"
                 : "=r"(a[0]), "=r"(a[1]), "=r"(a[2]), "=r"(a[3]) : "r"(saddr));
}

// ---------------- prep1: compose W2f = W2@Wf, Winf = Win@Wf, cbias ----------------
__global__ void __launch_bounds__(256)
prep1_kernel(const float* __restrict__ W_in, const float* __restrict__ b_in,
             const float* __restrict__ W2,   const float* __restrict__ b2,
             const float* __restrict__ Wf,   const float* __restrict__ bf)
{
    int idx = blockIdx.x * 256 + threadIdx.x;
    if (idx < 16384) {                         // W2f[k][n]
        int k = idx >> 7, n = idx & 127;
        float s = 0.f;
        for (int j = 0; j < 128; j++) s += W2[k * 128 + j] * Wf[j * 128 + n];
        g_W2f[idx] = s;
    } else if (idx < 16384 + 4096) {           // Winf[k][n], k<32 (zero past 23)
        int r = idx - 16384;
        int k = r >> 7, n = r & 127;
        float s = 0.f;
        if (k < 24)
            for (int j = 0; j < 128; j++) s += W_in[k * 128 + j] * Wf[j * 128 + n];
        g_Winf[r] = s;
    } else if (idx < 16384 + 4096 + 128) {     // cbias[n]
        int n = idx - (16384 + 4096);
        float s = bf[n];
        for (int j = 0; j < 128; j++) s += (b_in[j] + b2[j]) * Wf[j * 128 + n];
        g_cbias[n] = s;
    }
}

// ---------------- prep2: pack fragment-linear fp16 B arrays (uint4 pairs) ----------------
__global__ void __launch_bounds__(256)
prep2_kernel(const float* __restrict__ W_in, const float* __restrict__ W1)
{
    int idx = blockIdx.x * 256 + threadIdx.x;
    if (idx < 512) {                           // fWin from W_in (K=24 guard)
        int lane = idx & 31, ks = (idx >> 5) & 1, pg = idx >> 6;
        int k0 = ks * 16 + 2 * (lane & 3);
        int n0 = pg * 16 + (lane >> 2), n1 = n0 + 8;
        uint4 u;
        u.x = packh2(k0     < 24 ? W_in[k0 * 128 + n0]       : 0.f,
                     k0 + 1 < 24 ? W_in[(k0 + 1) * 128 + n0] : 0.f);
        u.y = packh2(k0 + 8 < 24 ? W_in[(k0 + 8) * 128 + n0] : 0.f,
                     k0 + 9 < 24 ? W_in[(k0 + 9) * 128 + n0] : 0.f);
        u.z = packh2(k0     < 24 ? W_in[k0 * 128 + n1]       : 0.f,
                     k0 + 1 < 24 ? W_in[(k0 + 1) * 128 + n1] : 0.f);
        u.w = packh2(k0 + 8 < 24 ? W_in[(k0 + 8) * 128 + n1] : 0.f,
                     k0 + 9 < 24 ? W_in[(k0 + 9) * 128 + n1] : 0.f);
        g_fWin[(pg * 2 + ks) * 32 + lane] = u;
    } else if (idx < 512 + 2048) {             // fW1 from W1
        int r = idx - 512;
        int lane = r & 31, ks = (r >> 5) & 7, pg = r >> 8;
        int k0 = ks * 16 + 2 * (lane & 3);
        int n0 = pg * 16 + (lane >> 2), n1 = n0 + 8;
        uint4 u;
        u.x = packh2(W1[k0 * 128 + n0],       W1[(k0 + 1) * 128 + n0]);
        u.y = packh2(W1[(k0 + 8) * 128 + n0], W1[(k0 + 9) * 128 + n0]);
        u.z = packh2(W1[k0 * 128 + n1],       W1[(k0 + 1) * 128 + n1]);
        u.w = packh2(W1[(k0 + 8) * 128 + n1], W1[(k0 + 9) * 128 + n1]);
        g_fW1[(pg * 8 + ks) * 32 + lane] = u;
    } else if (idx < 512 + 2048 + 2048) {      // fW2f from g_W2f
        int r = idx - (512 + 2048);
        int lane = r & 31, ks = (r >> 5) & 7, pg = r >> 8;
        int k0 = ks * 16 + 2 * (lane & 3);
        int n0 = pg * 16 + (lane >> 2), n1 = n0 + 8;
        uint4 u;
        u.x = packh2(g_W2f[k0 * 128 + n0],       g_W2f[(k0 + 1) * 128 + n0]);
        u.y = packh2(g_W2f[(k0 + 8) * 128 + n0], g_W2f[(k0 + 9) * 128 + n0]);
        u.z = packh2(g_W2f[k0 * 128 + n1],       g_W2f[(k0 + 1) * 128 + n1]);
        u.w = packh2(g_W2f[(k0 + 8) * 128 + n1], g_W2f[(k0 + 9) * 128 + n1]);
        g_fW2f[(pg * 8 + ks) * 32 + lane] = u;
    } else if (idx < 512 + 2048 + 2048 + 512) { // fWinf from g_Winf (32 rows, pre-zeroed)
        int r = idx - (512 + 2048 + 2048);
        int lane = r & 31, ks = (r >> 5) & 1, pg = r >> 6;
        int k0 = ks * 16 + 2 * (lane & 3);
        int n0 = pg * 16 + (lane >> 2), n1 = n0 + 8;
        uint4 u;
        u.x = packh2(g_Winf[k0 * 128 + n0],       g_Winf[(k0 + 1) * 128 + n0]);
        u.y = packh2(g_Winf[(k0 + 8) * 128 + n0], g_Winf[(k0 + 9) * 128 + n0]);
        u.z = packh2(g_Winf[k0 * 128 + n1],       g_Winf[(k0 + 1) * 128 + n1]);
        u.w = packh2(g_Winf[(k0 + 8) * 128 + n1], g_Winf[(k0 + 9) * 128 + n1]);
        g_fWinf[(pg * 2 + ks) * 32 + lane] = u;
    }
}

// ---------------- MMA stage: warp tile m32 x n64, ldmatrix A + uint4 B ----------------
// A tile: 256B/row, 16B chunk q at physical chunk q^(row&7).
template<int KS>
__device__ __forceinline__ void mma_stageA(
    float acc[2][8][4], uint32_t ra0, uint32_t ra1, int hi, int rs,
    const uint4* F, int nc, int lane)
{
#pragma unroll
    for (int ks = 0; ks < KS; ks++) {
        uint32_t a0[4], a1[4];
        uint32_t off = (uint32_t)(((2 * ks + hi) ^ rs) << 4);
        ldm4(a0, ra0 + off);
        ldm4(a1, ra1 + off);
#pragma unroll
        for (int p = 0; p < 4; p++) {
            uint4 b = F[((nc * 4 + p) * KS + ks) * 32 + lane];
            mma16(acc[0][2*p],   a0, b.x, b.y);
            mma16(acc[1][2*p],   a1, b.x, b.y);
            mma16(acc[0][2*p+1], a0, b.z, b.w);
            mma16(acc[1][2*p+1], a1, b.z, b.w);
        }
    }
}

// PE tile: 64B/row (4 chunks), chunk q at physical q^((row>>1)&3). B frags via __ldg.
__device__ __forceinline__ void mma_stagePE(
    float acc[2][8][4], uint32_t rp0, uint32_t rp1, int hi, int swp,
    const uint4* __restrict__ F, int nc, int lane)
{
#pragma unroll
    for (int ks = 0; ks < 2; ks++) {
        uint32_t a0[4], a1[4];
        uint32_t off = (uint32_t)(((2 * ks + hi) ^ swp) << 4);
        ldm4(a0, rp0 + off);
        ldm4(a1, rp1 + off);
#pragma unroll
        for (int p = 0; p < 4; p++) {
            uint4 b = __ldg(&F[((nc * 4 + p) * 2 + ks) * 32 + lane]);
            mma16(acc[0][2*p],   a0, b.x, b.y);
            mma16(acc[1][2*p],   a1, b.x, b.y);
            mma16(acc[0][2*p+1], a0, b.z, b.w);
            mma16(acc[1][2*p+1], a1, b.z, b.w);
        }
    }
}

// init accumulators with the stage bias (replaces zeroing + epilogue bias add)
__device__ __forceinline__ void bias_acc(
    float acc[2][8][4], const float* bias, int nbase, int t)
{
#pragma unroll
    for (int nt = 0; nt < 8; nt++) {
        float2 bb = *(const float2*)(bias + nbase + nt * 8 + 2 * t);
#pragma unroll
        for (int mt = 0; mt < 2; mt++) {
            acc[mt][nt][0] = bb.x; acc[mt][nt][1] = bb.y;
            acc[mt][nt][2] = bb.x; acc[mt][nt][3] = bb.y;
        }
    }
}

// gelu -> fp16 store to A (bias already folded into acc)
__device__ __forceinline__ void epilogueH(
    float acc[2][8][4], uint32_t* A32, int mbase, int nbase, int g, int t)
{
#pragma unroll
    for (int nt = 0; nt < 8; nt++) {
        int c = nbase + nt * 8 + 2 * t;
        int c2 = c >> 1;
        int w  = (((c2 >> 2) ^ g) << 2) + (c2 & 3);
#pragma unroll
        for (int mt = 0; mt < 2; mt++) {
            int r0 = mbase + mt * 16 + g;
            float v0 = gelu_f(acc[mt][nt][0]);
            float v1 = gelu_f(acc[mt][nt][1]);
            float v2 = gelu_f(acc[mt][nt][2]);
            float v3 = gelu_f(acc[mt][nt][3]);
            A32[r0 * 64 + w]       = packh2(v0, v1);
            A32[(r0 + 8) * 64 + w] = packh2(v2, v3);
        }
    }
}

// scores epilogue: fp32 into S with per-row 16B-chunk XOR swizzle (bias in acc)
__device__ __forceinline__ void epilogueS(
    float acc[2][8][4], float* S, int mbase, int nbase, int g, int t)
{
#pragma unroll
    for (int nt = 0; nt < 8; nt++) {
        int c = nbase + nt * 8 + 2 * t;
        int w = (((c >> 2) ^ g) << 2) + (c & 3);
#pragma unroll
        for (int mt = 0; mt < 2; mt++) {
            int r0 = mbase + mt * 16 + g;
            *(float2*)(S + r0 * 128 + w) =
                make_float2(acc[mt][nt][0], acc[mt][nt][1]);
            *(float2*)(S + (r0 + 8) * 128 + w) =
                make_float2(acc[mt][nt][2], acc[mt][nt][3]);
        }
    }
}

// ---------------- fused edge kernel (mma.sync fp16, 3 stages, 2 CTAs/SM) ----------------
__global__ void __launch_bounds__(256, 2)
edge_kernel(const int* __restrict__ pe_index, const float* __restrict__ pe_val,
            const float* __restrict__ b_in, const float* __restrict__ b1,
            const char* __restrict__ xh_b,
            char* __restrict__ wV_b, float* __restrict__ deg)
{
    extern __shared__ char smem[];
    uint32_t sm = s2u(smem);
    uint32_t* A32   = (uint32_t*)(smem + OFF_A);
    uint32_t* PE32  = (uint32_t*)(smem + OFF_PE);
    const uint4* F0 = (const uint4*)(smem + OFF_B0);
    const uint4* F1 = (const uint4*)(smem + OFF_B1);
    float* sBias    = (float*)(smem + OFF_BIAS);
    int*   sIdx     = (int*)(smem + OFF_IDX);

    int tid  = threadIdx.x;
    int wid  = tid >> 5, lane = tid & 31;
    int mr   = wid & 3,  nc   = wid >> 2;
    int g    = lane >> 2, t   = lane & 3;
    int mbase = mr * 32, nbase = nc * 64;
    int e0   = blockIdx.x * 128;

    // ldmatrix per-lane bases (A row = 256 bytes, PE row = 64 bytes)
    int l15 = lane & 15, hi = lane >> 4, rs = lane & 7;
    int swp = (l15 >> 1) & 3;
    uint32_t ra0 = sm + OFF_A  + (uint32_t)(mbase + l15) * 256;
    uint32_t ra1 = ra0 + 16 * 256;
    uint32_t rp0 = sm + OFF_PE + (uint32_t)(mbase + l15) * 64;
    uint32_t rp1 = rp0 + 16 * 64;

    // --- stage W1 -> B0, W2f -> B1 via cp.async ---
#pragma unroll
    for (int i = 0; i < 8; i++)
        cp16(sm + OFF_B0 + (i * 256 + tid) * 16, (const char*)g_fW1 + (i * 256 + tid) * 16);
    CP_COMMIT();
#pragma unroll
    for (int i = 0; i < 8; i++)
        cp16(sm + OFF_B1 + (i * 256 + tid) * 16, (const char*)g_fW2f + (i * 256 + tid) * 16);
    CP_COMMIT();

    // --- indices (pre-scaled to byte offsets: idx*512) + biases ---
    sIdx[tid] = ((tid < 128) ? pe_index[e0 + tid] : pe_index[NE + e0 + (tid - 128)]) << 9;
    {
        int c = tid & 127;
        if (tid < 128)      sBias[tid] = b_in[c];
        else                sBias[tid] = b1[c];
        if (tid < 128)      sBias[256 + tid] = g_cbias[tid];
    }

    // --- build PE tile (fp16, K 24 padded to 32) ---
    {
        int row = tid >> 1, half = tid & 1;
        const float4* pr = (const float4*)(pe_val + (size_t)(e0 + row) * 24) + half * 4;
        uint32_t w[8];
        if (half == 0) {
            float4 v0 = pr[0], v1 = pr[1], v2 = pr[2], v3 = pr[3];
            w[0] = packh2(v0.x, v0.y); w[1] = packh2(v0.z, v0.w);
            w[2] = packh2(v1.x, v1.y); w[3] = packh2(v1.z, v1.w);
            w[4] = packh2(v2.x, v2.y); w[5] = packh2(v2.z, v2.w);
            w[6] = packh2(v3.x, v3.y); w[7] = packh2(v3.z, v3.w);
        } else {
            float4 v0 = pr[0], v1 = pr[1];
            w[0] = packh2(v0.x, v0.y); w[1] = packh2(v0.z, v0.w);
            w[2] = packh2(v1.x, v1.y); w[3] = packh2(v1.z, v1.w);
            w[4] = w[5] = w[6] = w[7] = 0u;
        }
        int sw = (row >> 1) & 3;
        uint32_t* base = PE32 + row * 16;
        int q0 = half * 2, q1 = half * 2 + 1;
        *(uint4*)(base + ((q0 ^ sw) << 2)) = make_uint4(w[0], w[1], w[2], w[3]);
        *(uint4*)(base + ((q1 ^ sw) << 2)) = make_uint4(w[4], w[5], w[6], w[7]);
    }

    float acc[2][8][4];
    __syncthreads();                                 // PE + bias + idx visible

    // early degree atomics: drain in background under the MMA stages
    if (lane == 0) {
#pragma unroll 4
        for (int i = 0; i < 16; i++) {
            int off = sIdx[wid * 16 + i];
            red1((float*)((char*)deg + (off >> 7)), 1.0f);
        }
    }

    // ---- stage 1: acc = b_in + pe @ Win; A = gelu(acc) ----
    bias_acc(acc, sBias, nbase, t);
    mma_stagePE(acc, rp0, rp1, hi, swp, g_fWin, nc, lane);
    epilogueH(acc, A32, mbase, nbase, g, t);
    CP_WAIT(1);                                              // W1 resident
    __syncthreads();

    // ---- stage 2: acc = b1 + A @ W1; A = gelu(acc) ----
    bias_acc(acc, sBias + 128, nbase, t);
    mma_stageA<8>(acc, ra0, ra1, hi, rs, F0, nc, lane);
    __syncthreads();                                         // A reads done before overwrite
    epilogueH(acc, A32, mbase, nbase, g, t);
    CP_WAIT(0);                                              // W2f resident
    __syncthreads();

    // ---- stage 3 (composed): score = cbias + A @ W2f + pe @ Winf ----
    bias_acc(acc, sBias + 256, nbase, t);
    mma_stageA<8>(acc, ra0, ra1, hi, rs, F1, nc, lane);
    mma_stagePE(acc, rp0, rp1, hi, swp, g_fWinf, nc, lane);
    __syncthreads();                                         // B0/B1 reads done
    float* S = (float*)(smem + OFF_B0);                      // scores overlay 64KB
    epilogueS(acc, S, mbase, nbase, g, t);
    __syncthreads();

    // ---- scatter: msg = xh[src]*score -> wV[tgt] (byte-offset addressing) ----
#pragma unroll 4
    for (int i = 0; i < 16; i++) {
        int e    = wid * 16 + i;
        int toff = sIdx[e];
        int soff = sIdx[128 + e];
        float4 xv = *(const float4*)(xh_b + soff + lane * 16);
        float4 s4 = *(const float4*)(S + e * 128 + ((lane ^ (e & 7)) << 2));
        red4((float*)(wV_b + toff + lane * 16),
             xv.x * s4.x, xv.y * s4.y, xv.z * s4.z, xv.w * s4.w);
    }
}

// ---------------- node projection: xh = x @ W_x + b_x (16 nodes/block) ----------------
__global__ void __launch_bounds__(128)
xh_kernel(const float* __restrict__ x, const float* __restrict__ Wx,
          const float* __restrict__ bx, float* __restrict__ xh)
{
    __shared__ float sx[16][64];
    int tid = threadIdx.x;
    int n0  = blockIdx.x * 16;
    ((float4*)sx)[tid]       = ((const float4*)(x + (size_t)n0 * 64))[tid];
    ((float4*)sx)[tid + 128] = ((const float4*)(x + (size_t)n0 * 64))[tid + 128];
    __syncthreads();
    int c = tid;
    float s[16];
    float b = bx[c];
#pragma unroll
    for (int j = 0; j < 16; j++) s[j] = b;
#pragma unroll 8
    for (int k = 0; k < 64; k++) {
        float w = Wx[k * 128 + c];
#pragma unroll
        for (int j = 0; j < 16; j++) s[j] += sx[j][k] * w;
    }
#pragma unroll
    for (int j = 0; j < 16; j++)
        xh[(size_t)(n0 + j) * 128 + c] = s[j];
}

// ---------------- output projection (16 nodes/block, 4 nodes/thread) ----------------
__global__ void __launch_bounds__(256)
out_kernel(const float* __restrict__ wV, const float* __restrict__ deg,
           const float* __restrict__ hb, const float* __restrict__ Wout,
           const float* __restrict__ bout, float* __restrict__ out)
{
    __shared__ float sh[16][128];
    int tid = threadIdx.x;
    int n0  = blockIdx.x * 16;
#pragma unroll
    for (int i = tid; i < 2048; i += 256) {
        int nn = i >> 7, k = i & 127;
        int n  = n0 + nn;
        float d = deg[n];
        float invd = 1.0f / (d > 1.0f ? d : 1.0f);
        sh[nn][k] = wV[(size_t)n * 128 + k] * invd + hb[k];
    }
    __syncthreads();
    int gg = tid >> 6, c = tid & 63;
    float s0 = bout[c], s1 = s0, s2 = s0, s3 = s0;
#pragma unroll 8
    for (int k = 0; k < 128; k++) {
        float w = Wout[k * 64 + c];
        s0 += sh[4*gg+0][k] * w;
        s1 += sh[4*gg+1][k] * w;
        s2 += sh[4*gg+2][k] * w;
        s3 += sh[4*gg+3][k] * w;
    }
    out[(size_t)(n0 + 4*gg + 0) * 64 + c] = s0;
    out[(size_t)(n0 + 4*gg + 1) * 64 + c] = s1;
    out[(size_t)(n0 + 4*gg + 2) * 64 + c] = s2;
    out[(size_t)(n0 + 4*gg + 3) * 64 + c] = s3;
}

// ---------------- launch ----------------
extern "C" void kernel_launch(void* const* d_in, const int* in_sizes, int n_in,
                              void* d_out, int out_size)
{
    const float* x        = (const float*)d_in[0];
    const int*   pe_index = (const int*)  d_in[1];
    const float* pe_val   = (const float*)d_in[2];
    const float* W_in     = (const float*)d_in[3];
    const float* b_in     = (const float*)d_in[4];
    const float* W1       = (const float*)d_in[5];
    const float* b1       = (const float*)d_in[6];
    const float* W2       = (const float*)d_in[7];
    const float* b2       = (const float*)d_in[8];
    const float* W_fin    = (const float*)d_in[9];
    const float* b_fin    = (const float*)d_in[10];
    const float* W_x      = (const float*)d_in[11];
    const float* b_x      = (const float*)d_in[12];
    const float* head_b   = (const float*)d_in[13];
    const float* W_out    = (const float*)d_in[14];
    const float* b_out    = (const float*)d_in[15];
    float* out = (float*)d_out;

    void *p_xh, *p_wV, *p_deg;
    cudaGetSymbolAddress(&p_xh,  g_xh4);
    cudaGetSymbolAddress(&p_wV,  g_wV);
    cudaGetSymbolAddress(&p_deg, g_deg);

    cudaFuncSetAttribute(edge_kernel, cudaFuncAttributeMaxDynamicSharedMemorySize,
                         SMEM_TOT);

    cudaMemsetAsync(p_wV,  0, (size_t)NN * 128 * sizeof(float));
    cudaMemsetAsync(p_deg, 0, (size_t)NN * sizeof(float));

    prep1_kernel<<<81, 256>>>(W_in, b_in, W2, b2, W_fin, b_fin);
    prep2_kernel<<<20, 256>>>(W_in, W1);
    xh_kernel<<<NN / 16, 128>>>(x, W_x, b_x, (float*)p_xh);

    edge_kernel<<<NE / 128, 256, SMEM_TOT>>>(pe_index, pe_val,
        b_in, b1,
        (const char*)p_xh, (char*)p_wV, (float*)p_deg);

    out_kernel<<<NN / 16, 256>>>((const float*)p_wV, (const float*)p_deg,
                                 head_b, W_out, b_out, out);
}

// round 16
// speedup vs baseline: 1.3810x; 1.0016x over previous
#include <cuda_runtime.h>
#include <cuda_fp16.h>
#include <math.h>
#include <stdint.h>

#define NE  800000
#define NN  50000
#define HID 128

// ---------------- scratch (static device globals; no allocation) ----------------
__device__ float4 g_xh4[NN * 32];     // xh = x@W_x + b_x, [N,128] as float4
__device__ float  g_wV [NN * 128];    // scatter-add accumulator
__device__ float  g_deg[NN];          // degree accumulator
__device__ float  g_W2f [128 * 128];  // fp32 composed W2 @ Wf
__device__ float  g_Winf[32 * 128];   // fp32 composed Win @ Wf (rows 24..31 zero)
__device__ float  g_cbias[128];       // (b_in+b2) @ Wf + bf
// fragment-linear fp16 B operands, uint4 = frags for n-tile pair {2p, 2p+1}
__device__ uint4  g_fWin [8 * 2 * 32];   // 8 KB  (K padded to 32, zeros past 24)
__device__ uint4  g_fW1  [8 * 8 * 32];   // 32 KB
__device__ uint4  g_fW2f [8 * 8 * 32];   // 32 KB composed
__device__ uint4  g_fWinf[8 * 2 * 32];   // 8 KB composed

// ---------------- SMEM layout (edge kernel, dynamic) ----------------
#define OFF_A    0          // 32KB A tile: 128 rows x 128 fp16 (256B/row), XOR-swizzled
#define OFF_PE   32768      // 8KB  pe tile: 128 rows x 32 fp16 (64B/row)
#define OFF_B0   40960      // 32KB frag buffer 0 (W1)
#define OFF_B1   73728      // 32KB frag buffer 1 (W2f)
#define OFF_IDX  106496     // 1KB: tgt<<9 [128], src<<9 [128]
#define SMEM_TOT 107520
// scores overlay: fp32 [128][128] over B0+B1 (64KB exactly)

// pair barrier: the two warps sharing an mr group (64 threads), ids 1..4
#define BAR_PAIR(mr) asm volatile("bar.sync %0, 64;" :: "r"((mr) + 1) : "memory")

// ---------------- helpers ----------------
__device__ __forceinline__ uint32_t packh2(float lo, float hi) {
    __half2 h = __floats2half2_rn(lo, hi);
    return *(uint32_t*)&h;
}
// GELU exact-erf via Abramowitz-Stegun 7.1.25 (3-term, |err|<=2.5e-5), branchless.
__device__ __forceinline__ float gelu_f(float x) {
    float th = 0.5f * x;
    float u  = th * x;                                    // t^2 = x^2/2
    float at = 0.7071067811865476f * fabsf(x);            // t >= 0
    float d  = fmaf(0.47047f, at, 1.0f);
    float k;  asm("rcp.approx.f32 %0, %1;" : "=f"(k) : "f"(d));
    float p = fmaf(0.7478556f, k, -0.0958798f);
    p = fmaf(p, k, 0.3480242f);
    p = p * k;
    float s  = p * __expf(-u);                            // = 1 - erf(t)
    float ah = fabsf(th);
    return (th + ah) - ah * s;
}
__device__ __forceinline__ void red4(float* p, float a, float b, float c, float d) {
    asm volatile("red.global.add.v4.f32 [%0], {%1,%2,%3,%4};"
                 :: "l"(p), "f"(a), "f"(b), "f"(c), "f"(d) : "memory");
}
__device__ __forceinline__ void red1(float* p, float v) {
    asm volatile("red.global.add.f32 [%0], %1;" :: "l"(p), "f"(v) : "memory");
}
__device__ __forceinline__ uint32_t s2u(const void* p) {
    uint32_t a;
    asm("{ .reg .u64 t; cvta.to.shared.u64 t, %1; cvt.u32.u64 %0, t; }" : "=r"(a) : "l"(p));
    return a;
}
__device__ __forceinline__ void cp16(uint32_t s, const void* g) {
    asm volatile("cp.async.cg.shared.global [%0], [%1], 16;" :: "r"(s), "l"(g));
}
#define CP_COMMIT() asm volatile("cp.async.commit_group;")
#define CP_WAIT(n)  asm volatile("cp.async.wait_group %0;" :: "n"(n) : "memory")

__device__ __forceinline__ void mma16(float d[4], const uint32_t a[4],
                                      uint32_t b0, uint32_t b1) {
    asm volatile(
        "mma.sync.aligned.m16n8k16.row.col.f32.f16.f16.f32 "
        "{%0,%1,%2,%3},{%4,%5,%6,%7},{%8,%9},{%0,%1,%2,%3};"
        : "+f"(d[0]), "+f"(d[1]), "+f"(d[2]), "+f"(d[3])
        : "r"(a[0]), "r"(a[1]), "r"(a[2]), "r"(a[3]), "r"(b0), "r"(b1));
}
__device__ __forceinline__ void ldm4(uint32_t a[4], uint32_t saddr) {
    asm volatile("ldmatrix.sync.aligned.m8n8.x4.shared.b16 {%0,%1,%2,%3}, [%4];"
                 : "=r"(a[0]), "=r"(a[1]), "=r"(a[2]), "=r"(a[3]) : "r"(saddr));
}

// ---------------- prep1: compose W2f = W2@Wf, Winf = Win@Wf, cbias ----------------
__global__ void __launch_bounds__(256)
prep1_kernel(const float* __restrict__ W_in, const float* __restrict__ b_in,
             const float* __restrict__ W2,   const float* __restrict__ b2,
             const float* __restrict__ Wf,   const float* __restrict__ bf)
{
    int idx = blockIdx.x * 256 + threadIdx.x;
    if (idx < 16384) {                         // W2f[k][n]
        int k = idx >> 7, n = idx & 127;
        float s = 0.f;
        for (int j = 0; j < 128; j++) s += W2[k * 128 + j] * Wf[j * 128 + n];
        g_W2f[idx] = s;
    } else if (idx < 16384 + 4096) {           // Winf[k][n], k<32 (zero past 23)
        int r = idx - 16384;
        int k = r >> 7, n = r & 127;
        float s = 0.f;
        if (k < 24)
            for (int j = 0; j < 128; j++) s += W_in[k * 128 + j] * Wf[j * 128 + n];
        g_Winf[r] = s;
    } else if (idx < 16384 + 4096 + 128) {     // cbias[n]
        int n = idx - (16384 + 4096);
        float s = bf[n];
        for (int j = 0; j < 128; j++) s += (b_in[j] + b2[j]) * Wf[j * 128 + n];
        g_cbias[n] = s;
    }
}

// ---------------- prep2: pack fragment-linear fp16 B arrays (uint4 pairs) ----------------
__global__ void __launch_bounds__(256)
prep2_kernel(const float* __restrict__ W_in, const float* __restrict__ W1)
{
    int idx = blockIdx.x * 256 + threadIdx.x;
    if (idx < 512) {                           // fWin from W_in (K=24 guard)
        int lane = idx & 31, ks = (idx >> 5) & 1, pg = idx >> 6;
        int k0 = ks * 16 + 2 * (lane & 3);
        int n0 = pg * 16 + (lane >> 2), n1 = n0 + 8;
        uint4 u;
        u.x = packh2(k0     < 24 ? W_in[k0 * 128 + n0]       : 0.f,
                     k0 + 1 < 24 ? W_in[(k0 + 1) * 128 + n0] : 0.f);
        u.y = packh2(k0 + 8 < 24 ? W_in[(k0 + 8) * 128 + n0] : 0.f,
                     k0 + 9 < 24 ? W_in[(k0 + 9) * 128 + n0] : 0.f);
        u.z = packh2(k0     < 24 ? W_in[k0 * 128 + n1]       : 0.f,
                     k0 + 1 < 24 ? W_in[(k0 + 1) * 128 + n1] : 0.f);
        u.w = packh2(k0 + 8 < 24 ? W_in[(k0 + 8) * 128 + n1] : 0.f,
                     k0 + 9 < 24 ? W_in[(k0 + 9) * 128 + n1] : 0.f);
        g_fWin[(pg * 2 + ks) * 32 + lane] = u;
    } else if (idx < 512 + 2048) {             // fW1 from W1
        int r = idx - 512;
        int lane = r & 31, ks = (r >> 5) & 7, pg = r >> 8;
        int k0 = ks * 16 + 2 * (lane & 3);
        int n0 = pg * 16 + (lane >> 2), n1 = n0 + 8;
        uint4 u;
        u.x = packh2(W1[k0 * 128 + n0],       W1[(k0 + 1) * 128 + n0]);
        u.y = packh2(W1[(k0 + 8) * 128 + n0], W1[(k0 + 9) * 128 + n0]);
        u.z = packh2(W1[k0 * 128 + n1],       W1[(k0 + 1) * 128 + n1]);
        u.w = packh2(W1[(k0 + 8) * 128 + n1], W1[(k0 + 9) * 128 + n1]);
        g_fW1[(pg * 8 + ks) * 32 + lane] = u;
    } else if (idx < 512 + 2048 + 2048) {      // fW2f from g_W2f
        int r = idx - (512 + 2048);
        int lane = r & 31, ks = (r >> 5) & 7, pg = r >> 8;
        int k0 = ks * 16 + 2 * (lane & 3);
        int n0 = pg * 16 + (lane >> 2), n1 = n0 + 8;
        uint4 u;
        u.x = packh2(g_W2f[k0 * 128 + n0],       g_W2f[(k0 + 1) * 128 + n0]);
        u.y = packh2(g_W2f[(k0 + 8) * 128 + n0], g_W2f[(k0 + 9) * 128 + n0]);
        u.z = packh2(g_W2f[k0 * 128 + n1],       g_W2f[(k0 + 1) * 128 + n1]);
        u.w = packh2(g_W2f[(k0 + 8) * 128 + n1], g_W2f[(k0 + 9) * 128 + n1]);
        g_fW2f[(pg * 8 + ks) * 32 + lane] = u;
    } else if (idx < 512 + 2048 + 2048 + 512) { // fWinf from g_Winf (32 rows, pre-zeroed)
        int r = idx - (512 + 2048 + 2048);
        int lane = r & 31, ks = (r >> 5) & 1, pg = r >> 6;
        int k0 = ks * 16 + 2 * (lane & 3);
        int n0 = pg * 16 + (lane >> 2), n1 = n0 + 8;
        uint4 u;
        u.x = packh2(g_Winf[k0 * 128 + n0],       g_Winf[(k0 + 1) * 128 + n0]);
        u.y = packh2(g_Winf[(k0 + 8) * 128 + n0], g_Winf[(k0 + 9) * 128 + n0]);
        u.z = packh2(g_Winf[k0 * 128 + n1],       g_Winf[(k0 + 1) * 128 + n1]);
        u.w = packh2(g_Winf[(k0 + 8) * 128 + n1], g_Winf[(k0 + 9) * 128 + n1]);
        g_fWinf[(pg * 2 + ks) * 32 + lane] = u;
    }
}

// ---------------- MMA stage: warp tile m32 x n64, ldmatrix A + uint4 B ----------------
template<int KS>
__device__ __forceinline__ void mma_stageA(
    float acc[2][8][4], uint32_t ra0, uint32_t ra1, int hi, int rs,
    const uint4* F, int nc, int lane)
{
#pragma unroll
    for (int ks = 0; ks < KS; ks++) {
        uint32_t a0[4], a1[4];
        uint32_t off = (uint32_t)(((2 * ks + hi) ^ rs) << 4);
        ldm4(a0, ra0 + off);
        ldm4(a1, ra1 + off);
#pragma unroll
        for (int p = 0; p < 4; p++) {
            uint4 b = F[((nc * 4 + p) * KS + ks) * 32 + lane];
            mma16(acc[0][2*p],   a0, b.x, b.y);
            mma16(acc[1][2*p],   a1, b.x, b.y);
            mma16(acc[0][2*p+1], a0, b.z, b.w);
            mma16(acc[1][2*p+1], a1, b.z, b.w);
        }
    }
}

// PE tile: 64B/row (4 chunks), chunk q at physical q^((row>>1)&3). B frags via __ldg.
__device__ __forceinline__ void mma_stagePE(
    float acc[2][8][4], uint32_t rp0, uint32_t rp1, int hi, int swp,
    const uint4* __restrict__ F, int nc, int lane)
{
#pragma unroll
    for (int ks = 0; ks < 2; ks++) {
        uint32_t a0[4], a1[4];
        uint32_t off = (uint32_t)(((2 * ks + hi) ^ swp) << 4);
        ldm4(a0, rp0 + off);
        ldm4(a1, rp1 + off);
#pragma unroll
        for (int p = 0; p < 4; p++) {
            uint4 b = __ldg(&F[((nc * 4 + p) * 2 + ks) * 32 + lane]);
            mma16(acc[0][2*p],   a0, b.x, b.y);
            mma16(acc[1][2*p],   a1, b.x, b.y);
            mma16(acc[0][2*p+1], a0, b.z, b.w);
            mma16(acc[1][2*p+1], a1, b.z, b.w);
        }
    }
}

// init accumulators with the stage bias from GLOBAL memory (L2-hot broadcast)
__device__ __forceinline__ void bias_accG(
    float acc[2][8][4], const float* __restrict__ bias, int nbase, int t)
{
#pragma unroll
    for (int nt = 0; nt < 8; nt++) {
        float2 bb = __ldg((const float2*)(bias + nbase + nt * 8 + 2 * t));
#pragma unroll
        for (int mt = 0; mt < 2; mt++) {
            acc[mt][nt][0] = bb.x; acc[mt][nt][1] = bb.y;
            acc[mt][nt][2] = bb.x; acc[mt][nt][3] = bb.y;
        }
    }
}

// gelu -> fp16 store to A (bias already folded into acc)
__device__ __forceinline__ void epilogueH(
    float acc[2][8][4], uint32_t* A32, int mbase, int nbase, int g, int t)
{
#pragma unroll
    for (int nt = 0; nt < 8; nt++) {
        int c = nbase + nt * 8 + 2 * t;
        int c2 = c >> 1;
        int w  = (((c2 >> 2) ^ g) << 2) + (c2 & 3);
#pragma unroll
        for (int mt = 0; mt < 2; mt++) {
            int r0 = mbase + mt * 16 + g;
            float v0 = gelu_f(acc[mt][nt][0]);
            float v1 = gelu_f(acc[mt][nt][1]);
            float v2 = gelu_f(acc[mt][nt][2]);
            float v3 = gelu_f(acc[mt][nt][3]);
            A32[r0 * 64 + w]       = packh2(v0, v1);
            A32[(r0 + 8) * 64 + w] = packh2(v2, v3);
        }
    }
}

// scores epilogue: fp32 into S with per-row 16B-chunk XOR swizzle (bias in acc)
__device__ __forceinline__ void epilogueS(
    float acc[2][8][4], float* S, int mbase, int nbase, int g, int t)
{
#pragma unroll
    for (int nt = 0; nt < 8; nt++) {
        int c = nbase + nt * 8 + 2 * t;
        int w = (((c >> 2) ^ g) << 2) + (c & 3);
#pragma unroll
        for (int mt = 0; mt < 2; mt++) {
            int r0 = mbase + mt * 16 + g;
            *(float2*)(S + r0 * 128 + w) =
                make_float2(acc[mt][nt][0], acc[mt][nt][1]);
            *(float2*)(S + (r0 + 8) * 128 + w) =
                make_float2(acc[mt][nt][2], acc[mt][nt][3]);
        }
    }
}

// ---------------- fused edge kernel (pair-synchronized, 3 stages, 2 CTAs/SM) ----------------
__global__ void __launch_bounds__(256, 2)
edge_kernel(const int* __restrict__ pe_index, const float* __restrict__ pe_val,
            const float* __restrict__ b_in, const float* __restrict__ b1,
            const char* __restrict__ xh_b,
            char* __restrict__ wV_b, float* __restrict__ deg)
{
    extern __shared__ char smem[];
    uint32_t sm = s2u(smem);
    uint32_t* A32   = (uint32_t*)(smem + OFF_A);
    uint32_t* PE32  = (uint32_t*)(smem + OFF_PE);
    const uint4* F0 = (const uint4*)(smem + OFF_B0);
    const uint4* F1 = (const uint4*)(smem + OFF_B1);
    int*   sIdx     = (int*)(smem + OFF_IDX);

    int tid  = threadIdx.x;
    int wid  = tid >> 5, lane = tid & 31;
    int mr   = wid & 3,  nc   = wid >> 2;
    int g    = lane >> 2, t   = lane & 3;
    int mbase = mr * 32, nbase = nc * 64;
    int e0   = blockIdx.x * 128;

    // ldmatrix per-lane bases (A row = 256 bytes, PE row = 64 bytes)
    int l15 = lane & 15, hi = lane >> 4, rs = lane & 7;
    int swp = (l15 >> 1) & 3;
    uint32_t ra0 = sm + OFF_A  + (uint32_t)(mbase + l15) * 256;
    uint32_t ra1 = ra0 + 16 * 256;
    uint32_t rp0 = sm + OFF_PE + (uint32_t)(mbase + l15) * 64;
    uint32_t rp1 = rp0 + 16 * 64;

    // --- stage W1 -> B0, W2f -> B1 via cp.async (single group) ---
#pragma unroll
    for (int i = 0; i < 8; i++)
        cp16(sm + OFF_B0 + (i * 256 + tid) * 16, (const char*)g_fW1 + (i * 256 + tid) * 16);
#pragma unroll
    for (int i = 0; i < 8; i++)
        cp16(sm + OFF_B1 + (i * 256 + tid) * 16, (const char*)g_fW2f + (i * 256 + tid) * 16);
    CP_COMMIT();

    // --- warp-private: indices for own 16 scatter rows + early deg atomics ---
    {
        int srow = mbase + nc * 16 + (lane & 15);
        if (lane < 16) {
            int v = pe_index[e0 + srow];
            sIdx[srow] = v << 9;
            red1(deg + v, 1.0f);
        } else {
            int v = pe_index[NE + e0 + srow];
            sIdx[128 + srow] = v << 9;
        }
    }

    // --- warp-private: build PE rows [mbase+nc*16, +16), 2 threads/row ---
    {
        int row  = mbase + nc * 16 + (lane >> 1);
        int half = lane & 1;
        const float4* pr = (const float4*)(pe_val + (size_t)(e0 + row) * 24) + half * 4;
        uint32_t w[8];
        if (half == 0) {
            float4 v0 = pr[0], v1 = pr[1], v2 = pr[2], v3 = pr[3];
            w[0] = packh2(v0.x, v0.y); w[1] = packh2(v0.z, v0.w);
            w[2] = packh2(v1.x, v1.y); w[3] = packh2(v1.z, v1.w);
            w[4] = packh2(v2.x, v2.y); w[5] = packh2(v2.z, v2.w);
            w[6] = packh2(v3.x, v3.y); w[7] = packh2(v3.z, v3.w);
        } else {
            float4 v0 = pr[0], v1 = pr[1];
            w[0] = packh2(v0.x, v0.y); w[1] = packh2(v0.z, v0.w);
            w[2] = packh2(v1.x, v1.y); w[3] = packh2(v1.z, v1.w);
            w[4] = w[5] = w[6] = w[7] = 0u;
        }
        int sw = (row >> 1) & 3;
        uint32_t* base = PE32 + row * 16;
        int q0 = half * 2, q1 = half * 2 + 1;
        *(uint4*)(base + ((q0 ^ sw) << 2)) = make_uint4(w[0], w[1], w[2], w[3]);
        *(uint4*)(base + ((q1 ^ sw) << 2)) = make_uint4(w[4], w[5], w[6], w[7]);
    }
    BAR_PAIR(mr);                                    // pair's PE rows complete

    float acc[2][8][4];

    // ---- stage 1: acc = b_in + pe @ Win; A = gelu(acc) ----
    bias_accG(acc, b_in, nbase, t);
    mma_stagePE(acc, rp0, rp1, hi, swp, g_fWin, nc, lane);
    epilogueH(acc, A32, mbase, nbase, g, t);
    CP_WAIT(0);                                      // B0+B1 (own copies) done
    __syncthreads();                                 // all warps' cp.async visible; A pair-RAW

    // ---- stage 2: acc = b1 + A @ W1; A = gelu(acc) ----
    bias_accG(acc, b1, nbase, t);
    mma_stageA<8>(acc, ra0, ra1, hi, rs, F0, nc, lane);
    BAR_PAIR(mr);                                    // pair done reading my A col-half
    epilogueH(acc, A32, mbase, nbase, g, t);
    BAR_PAIR(mr);                                    // my new col-half visible to pair

    // ---- stage 3 (composed): score = cbias + A @ W2f + pe @ Winf ----
    bias_accG(acc, g_cbias, nbase, t);
    mma_stageA<8>(acc, ra0, ra1, hi, rs, F1, nc, lane);
    mma_stagePE(acc, rp0, rp1, hi, swp, g_fWinf, nc, lane);
    __syncthreads();                                 // ALL warps done with B0/B1
    float* S = (float*)(smem + OFF_B0);              // scores overlay 64KB
    epilogueS(acc, S, mbase, nbase, g, t);
    BAR_PAIR(mr);                                    // pair's score cols visible

    // ---- scatter: own 16 rows, msg = xh[src]*score -> wV[tgt] ----
#pragma unroll 4
    for (int i = 0; i < 16; i++) {
        int e    = mbase + nc * 16 + i;
        int toff = sIdx[e];
        int soff = sIdx[128 + e];
        float4 xv = *(const float4*)(xh_b + soff + lane * 16);
        float4 s4 = *(const float4*)(S + e * 128 + ((lane ^ (e & 7)) << 2));
        red4((float*)(wV_b + toff + lane * 16),
             xv.x * s4.x, xv.y * s4.y, xv.z * s4.z, xv.w * s4.w);
    }
}

// ---------------- node projection: xh = x @ W_x + b_x (16 nodes/block) ----------------
__global__ void __launch_bounds__(128)
xh_kernel(const float* __restrict__ x, const float* __restrict__ Wx,
          const float* __restrict__ bx, float* __restrict__ xh)
{
    __shared__ float sx[16][64];
    int tid = threadIdx.x;
    int n0  = blockIdx.x * 16;
    ((float4*)sx)[tid]       = ((const float4*)(x + (size_t)n0 * 64))[tid];
    ((float4*)sx)[tid + 128] = ((const float4*)(x + (size_t)n0 * 64))[tid + 128];
    __syncthreads();
    int c = tid;
    float s[16];
    float b = bx[c];
#pragma unroll
    for (int j = 0; j < 16; j++) s[j] = b;
#pragma unroll 8
    for (int k = 0; k < 64; k++) {
        float w = Wx[k * 128 + c];
#pragma unroll
        for (int j = 0; j < 16; j++) s[j] += sx[j][k] * w;
    }
#pragma unroll
    for (int j = 0; j < 16; j++)
        xh[(size_t)(n0 + j) * 128 + c] = s[j];
}

// ---------------- output projection (16 nodes/block, 4 nodes/thread) ----------------
__global__ void __launch_bounds__(256)
out_kernel(const float* __restrict__ wV, const float* __restrict__ deg,
           const float* __restrict__ hb, const float* __restrict__ Wout,
           const float* __restrict__ bout, float* __restrict__ out)
{
    __shared__ float sh[16][128];
    int tid = threadIdx.x;
    int n0  = blockIdx.x * 16;
#pragma unroll
    for (int i = tid; i < 2048; i += 256) {
        int nn = i >> 7, k = i & 127;
        int n  = n0 + nn;
        float d = deg[n];
        float invd = 1.0f / (d > 1.0f ? d : 1.0f);
        sh[nn][k] = wV[(size_t)n * 128 + k] * invd + hb[k];
    }
    __syncthreads();
    int gg = tid >> 6, c = tid & 63;
    float s0 = bout[c], s1 = s0, s2 = s0, s3 = s0;
#pragma unroll 8
    for (int k = 0; k < 128; k++) {
        float w = Wout[k * 64 + c];
        s0 += sh[4*gg+0][k] * w;
        s1 += sh[4*gg+1][k] * w;
        s2 += sh[4*gg+2][k] * w;
        s3 += sh[4*gg+3][k] * w;
    }
    out[(size_t)(n0 + 4*gg + 0) * 64 + c] = s0;
    out[(size_t)(n0 + 4*gg + 1) * 64 + c] = s1;
    out[(size_t)(n0 + 4*gg + 2) * 64 + c] = s2;
    out[(size_t)(n0 + 4*gg + 3) * 64 + c] = s3;
}

// ---------------- launch ----------------
extern "C" void kernel_launch(void* const* d_in, const int* in_sizes, int n_in,
                              void* d_out, int out_size)
{
    const float* x        = (const float*)d_in[0];
    const int*   pe_index = (const int*)  d_in[1];
    const float* pe_val   = (const float*)d_in[2];
    const float* W_in     = (const float*)d_in[3];
    const float* b_in     = (const float*)d_in[4];
    const float* W1       = (const float*)d_in[5];
    const float* b1       = (const float*)d_in[6];
    const float* W2       = (const float*)d_in[7];
    const float* b2       = (const float*)d_in[8];
    const float* W_fin    = (const float*)d_in[9];
    const float* b_fin    = (const float*)d_in[10];
    const float* W_x      = (const float*)d_in[11];
    const float* b_x      = (const float*)d_in[12];
    const float* head_b   = (const float*)d_in[13];
    const float* W_out    = (const float*)d_in[14];
    const float* b_out    = (const float*)d_in[15];
    float* out = (float*)d_out;

    void *p_xh, *p_wV, *p_deg;
    cudaGetSymbolAddress(&p_xh,  g_xh4);
    cudaGetSymbolAddress(&p_wV,  g_wV);
    cudaGetSymbolAddress(&p_deg, g_deg);

    cudaFuncSetAttribute(edge_kernel, cudaFuncAttributeMaxDynamicSharedMemorySize,
                         SMEM_TOT);

    cudaMemsetAsync(p_wV,  0, (size_t)NN * 128 * sizeof(float));
    cudaMemsetAsync(p_deg, 0, (size_t)NN * sizeof(float));

    prep1_kernel<<<81, 256>>>(W_in, b_in, W2, b2, W_fin, b_fin);
    prep2_kernel<<<20, 256>>>(W_in, W1);
    xh_kernel<<<NN / 16, 128>>>(x, W_x, b_x, (float*)p_xh);

    edge_kernel<<<NE / 128, 256, SMEM_TOT>>>(pe_index, pe_val,
        b_in, b1,
        (const char*)p_xh, (char*)p_wV, (float*)p_deg);

    out_kernel<<<NN / 16, 256>>>((const float*)p_wV, (const float*)p_deg,
                                 head_b, W_out, b_out, out);
}

// round 17
// speedup vs baseline: 1.3849x; 1.0028x over previous
#include <cuda_runtime.h>
#include <cuda_fp16.h>
#include <math.h>
#include <stdint.h>

#define NE  800000
#define NN  50000
#define HID 128

// ---------------- scratch (static device globals; no allocation) ----------------
__device__ float4 g_xh4[NN * 32];     // xh = x@W_x + b_x, [N,128] as float4
__device__ float  g_wV [NN * 128];    // scatter-add accumulator
__device__ float  g_deg[NN];          // degree accumulator
__device__ float  g_W2f [128 * 128];  // fp32 composed W2 @ Wf
__device__ float  g_Winf[32 * 128];   // fp32 composed Win @ Wf (rows 24..31 zero)
__device__ float  g_cbias[128];       // (b_in+b2) @ Wf + bf
// fragment-linear fp16 B operands, uint4 = frags for n-tile pair {2p, 2p+1}
__device__ uint4  g_fWin [8 * 2 * 32];   // 8 KB  (K padded to 32, zeros past 24)
__device__ uint4  g_fW1  [8 * 8 * 32];   // 32 KB
__device__ uint4  g_fW2f [8 * 8 * 32];   // 32 KB composed
__device__ uint4  g_fWinf[8 * 2 * 32];   // 8 KB composed

// ---------------- SMEM layout (edge kernel, dynamic) ----------------
#define OFF_A    0          // 32KB A tile: 128 rows x 128 fp16 (256B/row), XOR-swizzled
#define OFF_PE   32768      // 8KB  pe tile: 128 rows x 32 fp16 (64B/row)
#define OFF_B0   40960      // 32KB frag buffer 0 (W1)
#define OFF_B1   73728      // 32KB frag buffer 1 (W2f)
#define OFF_IDX  106496     // 1KB: tgt<<9 [128], src<<9 [128]
#define SMEM_TOT 107520
// scores overlay: fp32 [128][128] over B0+B1 (64KB exactly)

// pair barrier: the two warps sharing an mr group (64 threads), ids 1..4
#define BAR_PAIR(mr) asm volatile("bar.sync %0, 64;" :: "r"((mr) + 1) : "memory")

// ---------------- helpers ----------------
__device__ __forceinline__ uint32_t packh2(float lo, float hi) {
    __half2 h = __floats2half2_rn(lo, hi);
    return *(uint32_t*)&h;
}
// GELU exact-erf via Abramowitz-Stegun 7.1.25 (3-term, |err|<=2.5e-5), branchless.
__device__ __forceinline__ float gelu_f(float x) {
    float th = 0.5f * x;
    float u  = th * x;                                    // t^2 = x^2/2
    float at = 0.7071067811865476f * fabsf(x);            // t >= 0
    float d  = fmaf(0.47047f, at, 1.0f);
    float k;  asm("rcp.approx.f32 %0, %1;" : "=f"(k) : "f"(d));
    float p = fmaf(0.7478556f, k, -0.0958798f);
    p = fmaf(p, k, 0.3480242f);
    p = p * k;
    float s  = p * __expf(-u);                            // = 1 - erf(t)
    float ah = fabsf(th);
    return (th + ah) - ah * s;
}
__device__ __forceinline__ void red4(float* p, float a, float b, float c, float d) {
    asm volatile("red.global.add.v4.f32 [%0], {%1,%2,%3,%4};"
                 :: "l"(p), "f"(a), "f"(b), "f"(c), "f"(d) : "memory");
}
__device__ __forceinline__ void red1(float* p, float v) {
    asm volatile("red.global.add.f32 [%0], %1;" :: "l"(p), "f"(v) : "memory");
}
__device__ __forceinline__ uint32_t s2u(const void* p) {
    uint32_t a;
    asm("{ .reg .u64 t; cvta.to.shared.u64 t, %1; cvt.u32.u64 %0, t; }" : "=r"(a) : "l"(p));
    return a;
}
__device__ __forceinline__ void cp16(uint32_t s, const void* g) {
    asm volatile("cp.async.cg.shared.global [%0], [%1], 16;" :: "r"(s), "l"(g));
}
#define CP_COMMIT() asm volatile("cp.async.commit_group;")
#define CP_WAIT(n)  asm volatile("cp.async.wait_group %0;" :: "n"(n) : "memory")

__device__ __forceinline__ void mma16(float d[4], const uint32_t a[4],
                                      uint32_t b0, uint32_t b1) {
    asm volatile(
        "mma.sync.aligned.m16n8k16.row.col.f32.f16.f16.f32 "
        "{%0,%1,%2,%3},{%4,%5,%6,%7},{%8,%9},{%0,%1,%2,%3};"
        : "+f"(d[0]), "+f"(d[1]), "+f"(d[2]), "+f"(d[3])
        : "r"(a[0]), "r"(a[1]), "r"(a[2]), "r"(a[3]), "r"(b0), "r"(b1));
}
__device__ __forceinline__ void ldm4(uint32_t a[4], uint32_t saddr) {
    asm volatile("ldmatrix.sync.aligned.m8n8.x4.shared.b16 {%0,%1,%2,%3}, [%4];"
                 : "=r"(a[0]), "=r"(a[1]), "=r"(a[2]), "=r"(a[3]) : "r"(saddr));
}

// ---------------- prep1: compose W2f = W2@Wf, Winf = Win@Wf, cbias ----------------
__global__ void __launch_bounds__(256)
prep1_kernel(const float* __restrict__ W_in, const float* __restrict__ b_in,
             const float* __restrict__ W2,   const float* __restrict__ b2,
             const float* __restrict__ Wf,   const float* __restrict__ bf)
{
    int idx = blockIdx.x * 256 + threadIdx.x;
    if (idx < 16384) {                         // W2f[k][n]
        int k = idx >> 7, n = idx & 127;
        float s = 0.f;
        for (int j = 0; j < 128; j++) s += W2[k * 128 + j] * Wf[j * 128 + n];
        g_W2f[idx] = s;
    } else if (idx < 16384 + 4096) {           // Winf[k][n], k<32 (zero past 23)
        int r = idx - 16384;
        int k = r >> 7, n = r & 127;
        float s = 0.f;
        if (k < 24)
            for (int j = 0; j < 128; j++) s += W_in[k * 128 + j] * Wf[j * 128 + n];
        g_Winf[r] = s;
    } else if (idx < 16384 + 4096 + 128) {     // cbias[n]
        int n = idx - (16384 + 4096);
        float s = bf[n];
        for (int j = 0; j < 128; j++) s += (b_in[j] + b2[j]) * Wf[j * 128 + n];
        g_cbias[n] = s;
    }
}

// ---------------- prep2: pack fragment-linear fp16 B arrays (uint4 pairs) ----------------
__global__ void __launch_bounds__(256)
prep2_kernel(const float* __restrict__ W_in, const float* __restrict__ W1)
{
    int idx = blockIdx.x * 256 + threadIdx.x;
    if (idx < 512) {                           // fWin from W_in (K=24 guard)
        int lane = idx & 31, ks = (idx >> 5) & 1, pg = idx >> 6;
        int k0 = ks * 16 + 2 * (lane & 3);
        int n0 = pg * 16 + (lane >> 2), n1 = n0 + 8;
        uint4 u;
        u.x = packh2(k0     < 24 ? W_in[k0 * 128 + n0]       : 0.f,
                     k0 + 1 < 24 ? W_in[(k0 + 1) * 128 + n0] : 0.f);
        u.y = packh2(k0 + 8 < 24 ? W_in[(k0 + 8) * 128 + n0] : 0.f,
                     k0 + 9 < 24 ? W_in[(k0 + 9) * 128 + n0] : 0.f);
        u.z = packh2(k0     < 24 ? W_in[k0 * 128 + n1]       : 0.f,
                     k0 + 1 < 24 ? W_in[(k0 + 1) * 128 + n1] : 0.f);
        u.w = packh2(k0 + 8 < 24 ? W_in[(k0 + 8) * 128 + n1] : 0.f,
                     k0 + 9 < 24 ? W_in[(k0 + 9) * 128 + n1] : 0.f);
        g_fWin[(pg * 2 + ks) * 32 + lane] = u;
    } else if (idx < 512 + 2048) {             // fW1 from W1
        int r = idx - 512;
        int lane = r & 31, ks = (r >> 5) & 7, pg = r >> 8;
        int k0 = ks * 16 + 2 * (lane & 3);
        int n0 = pg * 16 + (lane >> 2), n1 = n0 + 8;
        uint4 u;
        u.x = packh2(W1[k0 * 128 + n0],       W1[(k0 + 1) * 128 + n0]);
        u.y = packh2(W1[(k0 + 8) * 128 + n0], W1[(k0 + 9) * 128 + n0]);
        u.z = packh2(W1[k0 * 128 + n1],       W1[(k0 + 1) * 128 + n1]);
        u.w = packh2(W1[(k0 + 8) * 128 + n1], W1[(k0 + 9) * 128 + n1]);
        g_fW1[(pg * 8 + ks) * 32 + lane] = u;
    } else if (idx < 512 + 2048 + 2048) {      // fW2f from g_W2f
        int r = idx - (512 + 2048);
        int lane = r & 31, ks = (r >> 5) & 7, pg = r >> 8;
        int k0 = ks * 16 + 2 * (lane & 3);
        int n0 = pg * 16 + (lane >> 2), n1 = n0 + 8;
        uint4 u;
        u.x = packh2(g_W2f[k0 * 128 + n0],       g_W2f[(k0 + 1) * 128 + n0]);
        u.y = packh2(g_W2f[(k0 + 8) * 128 + n0], g_W2f[(k0 + 9) * 128 + n0]);
        u.z = packh2(g_W2f[k0 * 128 + n1],       g_W2f[(k0 + 1) * 128 + n1]);
        u.w = packh2(g_W2f[(k0 + 8) * 128 + n1], g_W2f[(k0 + 9) * 128 + n1]);
        g_fW2f[(pg * 8 + ks) * 32 + lane] = u;
    } else if (idx < 512 + 2048 + 2048 + 512) { // fWinf from g_Winf (32 rows, pre-zeroed)
        int r = idx - (512 + 2048 + 2048);
        int lane = r & 31, ks = (r >> 5) & 1, pg = r >> 6;
        int k0 = ks * 16 + 2 * (lane & 3);
        int n0 = pg * 16 + (lane >> 2), n1 = n0 + 8;
        uint4 u;
        u.x = packh2(g_Winf[k0 * 128 + n0],       g_Winf[(k0 + 1) * 128 + n0]);
        u.y = packh2(g_Winf[(k0 + 8) * 128 + n0], g_Winf[(k0 + 9) * 128 + n0]);
        u.z = packh2(g_Winf[k0 * 128 + n1],       g_Winf[(k0 + 1) * 128 + n1]);
        u.w = packh2(g_Winf[(k0 + 8) * 128 + n1], g_Winf[(k0 + 9) * 128 + n1]);
        g_fWinf[(pg * 2 + ks) * 32 + lane] = u;
    }
}

// ---------------- MMA stage: warp tile m32 x n64, ldmatrix A + uint4 B ----------------
template<int KS>
__device__ __forceinline__ void mma_stageA(
    float acc[2][8][4], uint32_t ra0, uint32_t ra1, int hi, int rs,
    const uint4* F, int nc, int lane)
{
#pragma unroll
    for (int ks = 0; ks < KS; ks++) {
        uint32_t a0[4], a1[4];
        uint32_t off = (uint32_t)(((2 * ks + hi) ^ rs) << 4);
        ldm4(a0, ra0 + off);
        ldm4(a1, ra1 + off);
#pragma unroll
        for (int p = 0; p < 4; p++) {
            uint4 b = F[((nc * 4 + p) * KS + ks) * 32 + lane];
            mma16(acc[0][2*p],   a0, b.x, b.y);
            mma16(acc[1][2*p],   a1, b.x, b.y);
            mma16(acc[0][2*p+1], a0, b.z, b.w);
            mma16(acc[1][2*p+1], a1, b.z, b.w);
        }
    }
}

// PE tile: 64B/row (4 chunks), chunk q at physical q^((row>>1)&3). B frags via __ldg.
__device__ __forceinline__ void mma_stagePE(
    float acc[2][8][4], uint32_t rp0, uint32_t rp1, int hi, int swp,
    const uint4* __restrict__ F, int nc, int lane)
{
#pragma unroll
    for (int ks = 0; ks < 2; ks++) {
        uint32_t a0[4], a1[4];
        uint32_t off = (uint32_t)(((2 * ks + hi) ^ swp) << 4);
        ldm4(a0, rp0 + off);
        ldm4(a1, rp1 + off);
#pragma unroll
        for (int p = 0; p < 4; p++) {
            uint4 b = __ldg(&F[((nc * 4 + p) * 2 + ks) * 32 + lane]);
            mma16(acc[0][2*p],   a0, b.x, b.y);
            mma16(acc[1][2*p],   a1, b.x, b.y);
            mma16(acc[0][2*p+1], a0, b.z, b.w);
            mma16(acc[1][2*p+1], a1, b.z, b.w);
        }
    }
}

// init accumulators with the stage bias from GLOBAL memory (L2-hot broadcast)
__device__ __forceinline__ void bias_accG(
    float acc[2][8][4], const float* __restrict__ bias, int nbase, int t)
{
#pragma unroll
    for (int nt = 0; nt < 8; nt++) {
        float2 bb = __ldg((const float2*)(bias + nbase + nt * 8 + 2 * t));
#pragma unroll
        for (int mt = 0; mt < 2; mt++) {
            acc[mt][nt][0] = bb.x; acc[mt][nt][1] = bb.y;
            acc[mt][nt][2] = bb.x; acc[mt][nt][3] = bb.y;
        }
    }
}

// gelu -> fp16 store to A (bias already folded into acc)
__device__ __forceinline__ void epilogueH(
    float acc[2][8][4], uint32_t* A32, int mbase, int nbase, int g, int t)
{
#pragma unroll
    for (int nt = 0; nt < 8; nt++) {
        int c = nbase + nt * 8 + 2 * t;
        int c2 = c >> 1;
        int w  = (((c2 >> 2) ^ g) << 2) + (c2 & 3);
#pragma unroll
        for (int mt = 0; mt < 2; mt++) {
            int r0 = mbase + mt * 16 + g;
            float v0 = gelu_f(acc[mt][nt][0]);
            float v1 = gelu_f(acc[mt][nt][1]);
            float v2 = gelu_f(acc[mt][nt][2]);
            float v3 = gelu_f(acc[mt][nt][3]);
            A32[r0 * 64 + w]       = packh2(v0, v1);
            A32[(r0 + 8) * 64 + w] = packh2(v2, v3);
        }
    }
}

// scores epilogue: fp32 into S with per-row 16B-chunk XOR swizzle (bias in acc)
__device__ __forceinline__ void epilogueS(
    float acc[2][8][4], float* S, int mbase, int nbase, int g, int t)
{
#pragma unroll
    for (int nt = 0; nt < 8; nt++) {
        int c = nbase + nt * 8 + 2 * t;
        int w = (((c >> 2) ^ g) << 2) + (c & 3);
#pragma unroll
        for (int mt = 0; mt < 2; mt++) {
            int r0 = mbase + mt * 16 + g;
            *(float2*)(S + r0 * 128 + w) =
                make_float2(acc[mt][nt][0], acc[mt][nt][1]);
            *(float2*)(S + (r0 + 8) * 128 + w) =
                make_float2(acc[mt][nt][2], acc[mt][nt][3]);
        }
    }
}

// ---------------- fused edge kernel (pair-synchronized, 3 stages, 2 CTAs/SM) ----------------
__global__ void __launch_bounds__(256, 2)
edge_kernel(const int* __restrict__ pe_index, const float* __restrict__ pe_val,
            const float* __restrict__ b_in, const float* __restrict__ b1,
            const char* __restrict__ xh_b,
            char* __restrict__ wV_b, float* __restrict__ deg)
{
    extern __shared__ char smem[];
    uint32_t sm = s2u(smem);
    uint32_t* A32   = (uint32_t*)(smem + OFF_A);
    uint32_t* PE32  = (uint32_t*)(smem + OFF_PE);
    const uint4* F0 = (const uint4*)(smem + OFF_B0);
    const uint4* F1 = (const uint4*)(smem + OFF_B1);
    int*   sIdx     = (int*)(smem + OFF_IDX);

    int tid  = threadIdx.x;
    int wid  = tid >> 5, lane = tid & 31;
    int mr   = wid & 3,  nc   = wid >> 2;
    int g    = lane >> 2, t   = lane & 3;
    int mbase = mr * 32, nbase = nc * 64;
    int e0   = blockIdx.x * 128;

    // ldmatrix per-lane bases (A row = 256 bytes, PE row = 64 bytes)
    int l15 = lane & 15, hi = lane >> 4, rs = lane & 7;
    int swp = (l15 >> 1) & 3;
    uint32_t ra0 = sm + OFF_A  + (uint32_t)(mbase + l15) * 256;
    uint32_t ra1 = ra0 + 16 * 256;
    uint32_t rp0 = sm + OFF_PE + (uint32_t)(mbase + l15) * 64;
    uint32_t rp1 = rp0 + 16 * 64;

    // --- stage W1 -> B0, W2f -> B1 via cp.async (single group) ---
#pragma unroll
    for (int i = 0; i < 8; i++)
        cp16(sm + OFF_B0 + (i * 256 + tid) * 16, (const char*)g_fW1 + (i * 256 + tid) * 16);
#pragma unroll
    for (int i = 0; i < 8; i++)
        cp16(sm + OFF_B1 + (i * 256 + tid) * 16, (const char*)g_fW2f + (i * 256 + tid) * 16);
    CP_COMMIT();

    // --- warp-private: indices for own 16 scatter rows + early deg atomics ---
    {
        int srow = mbase + nc * 16 + (lane & 15);
        if (lane < 16) {
            int v = pe_index[e0 + srow];
            sIdx[srow] = v << 9;
            red1(deg + v, 1.0f);
        } else {
            int v = pe_index[NE + e0 + srow];
            sIdx[128 + srow] = v << 9;
        }
    }

    // --- warp-private: build PE rows [mbase+nc*16, +16), 2 threads/row ---
    {
        int row  = mbase + nc * 16 + (lane >> 1);
        int half = lane & 1;
        const float4* pr = (const float4*)(pe_val + (size_t)(e0 + row) * 24) + half * 4;
        uint32_t w[8];
        if (half == 0) {
            float4 v0 = pr[0], v1 = pr[1], v2 = pr[2], v3 = pr[3];
            w[0] = packh2(v0.x, v0.y); w[1] = packh2(v0.z, v0.w);
            w[2] = packh2(v1.x, v1.y); w[3] = packh2(v1.z, v1.w);
            w[4] = packh2(v2.x, v2.y); w[5] = packh2(v2.z, v2.w);
            w[6] = packh2(v3.x, v3.y); w[7] = packh2(v3.z, v3.w);
        } else {
            float4 v0 = pr[0], v1 = pr[1];
            w[0] = packh2(v0.x, v0.y); w[1] = packh2(v0.z, v0.w);
            w[2] = packh2(v1.x, v1.y); w[3] = packh2(v1.z, v1.w);
            w[4] = w[5] = w[6] = w[7] = 0u;
        }
        int sw = (row >> 1) & 3;
        uint32_t* base = PE32 + row * 16;
        int q0 = half * 2, q1 = half * 2 + 1;
        *(uint4*)(base + ((q0 ^ sw) << 2)) = make_uint4(w[0], w[1], w[2], w[3]);
        *(uint4*)(base + ((q1 ^ sw) << 2)) = make_uint4(w[4], w[5], w[6], w[7]);
    }
    BAR_PAIR(mr);                                    // pair's PE rows complete

    float acc[2][8][4];

    // ---- stage 1: acc = b_in + pe @ Win; A = gelu(acc) ----
    bias_accG(acc, b_in, nbase, t);
    mma_stagePE(acc, rp0, rp1, hi, swp, g_fWin, nc, lane);
    epilogueH(acc, A32, mbase, nbase, g, t);
    CP_WAIT(0);                                      // B0+B1 (own copies) done
    __syncthreads();                                 // all warps' cp.async visible; A pair-RAW

    // ---- stage 2: acc = b1 + A @ W1; A = gelu(acc) ----
    bias_accG(acc, b1, nbase, t);
    mma_stageA<8>(acc, ra0, ra1, hi, rs, F0, nc, lane);
    BAR_PAIR(mr);                                    // pair done reading my A col-half
    epilogueH(acc, A32, mbase, nbase, g, t);
    BAR_PAIR(mr);                                    // my new col-half visible to pair

    // ---- stage 3 (composed): score = cbias + A @ W2f + pe @ Winf ----
    bias_accG(acc, g_cbias, nbase, t);
    mma_stageA<8>(acc, ra0, ra1, hi, rs, F1, nc, lane);
    mma_stagePE(acc, rp0, rp1, hi, swp, g_fWinf, nc, lane);
    __syncthreads();                                 // ALL warps done with B0/B1
    float* S = (float*)(smem + OFF_B0);              // scores overlay 64KB
    epilogueS(acc, S, mbase, nbase, g, t);
    BAR_PAIR(mr);                                    // pair's score cols visible

    // ---- scatter: own 16 rows, msg = xh[src]*score -> wV[tgt] ----
#pragma unroll 4
    for (int i = 0; i < 16; i++) {
        int e    = mbase + nc * 16 + i;
        int toff = sIdx[e];
        int soff = sIdx[128 + e];
        float4 xv = *(const float4*)(xh_b + soff + lane * 16);
        float4 s4 = *(const float4*)(S + e * 128 + ((lane ^ (e & 7)) << 2));
        red4((float*)(wV_b + toff + lane * 16),
             xv.x * s4.x, xv.y * s4.y, xv.z * s4.z, xv.w * s4.w);
    }
}

// ---------------- node projection: xh = x @ W_x + b_x (16 nodes/block) ----------------
__global__ void __launch_bounds__(128)
xh_kernel(const float* __restrict__ x, const float* __restrict__ Wx,
          const float* __restrict__ bx, float* __restrict__ xh)
{
    __shared__ float sx[16][64];
    int tid = threadIdx.x;
    int n0  = blockIdx.x * 16;
    ((float4*)sx)[tid]       = ((const float4*)(x + (size_t)n0 * 64))[tid];
    ((float4*)sx)[tid + 128] = ((const float4*)(x + (size_t)n0 * 64))[tid + 128];
    __syncthreads();
    int c = tid;
    float s[16];
    float b = bx[c];
#pragma unroll
    for (int j = 0; j < 16; j++) s[j] = b;
#pragma unroll 8
    for (int k = 0; k < 64; k++) {
        float w = Wx[k * 128 + c];
#pragma unroll
        for (int j = 0; j < 16; j++) s[j] += sx[j][k] * w;
    }
#pragma unroll
    for (int j = 0; j < 16; j++)
        xh[(size_t)(n0 + j) * 128 + c] = s[j];
}

// ---------------- output projection (16 nodes/block, 4 nodes/thread) ----------------
__global__ void __launch_bounds__(256)
out_kernel(const float* __restrict__ wV, const float* __restrict__ deg,
           const float* __restrict__ hb, const float* __restrict__ Wout,
           const float* __restrict__ bout, float* __restrict__ out)
{
    __shared__ float sh[16][128];
    int tid = threadIdx.x;
    int n0  = blockIdx.x * 16;
#pragma unroll
    for (int i = tid; i < 2048; i += 256) {
        int nn = i >> 7, k = i & 127;
        int n  = n0 + nn;
        float d = deg[n];
        float invd = 1.0f / (d > 1.0f ? d : 1.0f);
        sh[nn][k] = wV[(size_t)n * 128 + k] * invd + hb[k];
    }
    __syncthreads();
    int gg = tid >> 6, c = tid & 63;
    float s0 = bout[c], s1 = s0, s2 = s0, s3 = s0;
#pragma unroll 8
    for (int k = 0; k < 128; k++) {
        float w = Wout[k * 64 + c];
        s0 += sh[4*gg+0][k] * w;
        s1 += sh[4*gg+1][k] * w;
        s2 += sh[4*gg+2][k] * w;
        s3 += sh[4*gg+3][k] * w;
    }
    out[(size_t)(n0 + 4*gg + 0) * 64 + c] = s0;
    out[(size_t)(n0 + 4*gg + 1) * 64 + c] = s1;
    out[(size_t)(n0 + 4*gg + 2) * 64 + c] = s2;
    out[(size_t)(n0 + 4*gg + 3) * 64 + c] = s3;
}

// ---------------- launch ----------------
extern "C" void kernel_launch(void* const* d_in, const int* in_sizes, int n_in,
                              void* d_out, int out_size)
{
    const float* x        = (const float*)d_in[0];
    const int*   pe_index = (const int*)  d_in[1];
    const float* pe_val   = (const float*)d_in[2];
    const float* W_in     = (const float*)d_in[3];
    const float* b_in     = (const float*)d_in[4];
    const float* W1       = (const float*)d_in[5];
    const float* b1       = (const float*)d_in[6];
    const float* W2       = (const float*)d_in[7];
    const float* b2       = (const float*)d_in[8];
    const float* W_fin    = (const float*)d_in[9];
    const float* b_fin    = (const float*)d_in[10];
    const float* W_x      = (const float*)d_in[11];
    const float* b_x      = (const float*)d_in[12];
    const float* head_b   = (const float*)d_in[13];
    const float* W_out    = (const float*)d_in[14];
    const float* b_out    = (const float*)d_in[15];
    float* out = (float*)d_out;

    void *p_xh, *p_wV, *p_deg;
    cudaGetSymbolAddress(&p_xh,  g_xh4);
    cudaGetSymbolAddress(&p_wV,  g_wV);
    cudaGetSymbolAddress(&p_deg, g_deg);

    cudaFuncSetAttribute(edge_kernel, cudaFuncAttributeMaxDynamicSharedMemorySize,
                         SMEM_TOT);

    cudaMemsetAsync(p_wV,  0, (size_t)NN * 128 * sizeof(float));
    cudaMemsetAsync(p_deg, 0, (size_t)NN * sizeof(float));

    prep1_kernel<<<81, 256>>>(W_in, b_in, W2, b2, W_fin, b_fin);
    prep2_kernel<<<20, 256>>>(W_in, W1);
    xh_kernel<<<NN / 16, 128>>>(x, W_x, b_x, (float*)p_xh);

    edge_kernel<<<NE / 128, 256, SMEM_TOT>>>(pe_index, pe_val,
        b_in, b1,
        (const char*)p_xh, (char*)p_wV, (float*)p_deg);

    out_kernel<<<NN / 16, 256>>>((const float*)p_wV, (const float*)p_deg,
                                 head_b, W_out, b_out, out);
}